// round 14
// baseline (speedup 1.0000x reference)
#include <cuda_runtime.h>
#include <cuda_fp16.h>
#include <math.h>
#include <stdint.h>

#define NB 4
#define NC 256
#define NPIX 4096
#define STR 80
#define ISC (1.0f/256.0f)

// ---- static device scratch ----
__device__ __half g_xt_h[(size_t)NB*4356*256];   // padded x fp16 hi, [b][pix66][c]
__device__ __half g_xt_l[(size_t)NB*4356*256];   // (x-hi)*256
__device__ __half g_wqh[NC*4608];                // Wq [h(2304) | l*256(2304)], k=t*256+c
__device__ __half g_wkh[NC*512];
__device__ __half g_wvh[NC*512];
__device__ float g_qc[(size_t)NB*NC*NPIX];
__device__ float g_kc[(size_t)NB*NC*NPIX];
__device__ float g_vc[(size_t)NB*NC*NPIX];
__device__ __half g_qth[(size_t)NB*NPIX*512];    // BN(Q)^T [h|l]
__device__ __half g_kth[(size_t)NB*NPIX*512];    // BN(K)^T [h|l]
__device__ __half g_vf[(size_t)NB*NC*NPIX];      // BN(V) fp16 [b][c][k]
__device__ __half g_P16[(size_t)NB*NPIX*NPIX];   // exp(s-lm) fp16 [b][q][k]
__device__ float g_pm[(size_t)NB*128*NPIX];      // per-32k-group max
__device__ float g_ps[(size_t)NB*128*NPIX];      // per-32k-group sum
__device__ float g_psum1[3*128*256];             // conv partial sums [t][slot][ch]
__device__ float g_psum2[3*128*256];
__device__ float g_sbp[8*NB*NPIX];               // border-score partials [cblk][b*q]
__device__ float g_bw[NB*NPIX];
__device__ float g_m[NB*NPIX];
__device__ float g_iz[NB*NPIX];
__device__ float g_a[3*NC];
__device__ float g_dd[3*NC];
__device__ float g_kbv[NC];
__device__ float g_vbv[NC];

// ---- helpers ----
__device__ __forceinline__ uint32_t smem_u32(const void* p) {
    uint32_t a;
    asm("{ .reg .u64 t; cvta.to.shared.u64 t, %1; cvt.u32.u64 %0, t; }" : "=r"(a) : "l"(p));
    return a;
}
__device__ __forceinline__ void cpa16(uint32_t s, const void* g) {
    asm volatile("cp.async.cg.shared.global [%0], [%1], 16;" :: "r"(s), "l"(g));
}
__device__ __forceinline__ void ldm4(uint32_t* r, uint32_t addr) {
    asm volatile("ldmatrix.sync.aligned.m8n8.x4.shared.b16 {%0,%1,%2,%3}, [%4];"
                 : "=r"(r[0]), "=r"(r[1]), "=r"(r[2]), "=r"(r[3]) : "r"(addr));
}
// fp16 data, f32 accum
__device__ __forceinline__ void mma16h(float* d, const uint32_t* a, uint32_t b0, uint32_t b1) {
    asm volatile(
        "mma.sync.aligned.m16n8k16.row.col.f32.f16.f16.f32 "
        "{%0,%1,%2,%3}, {%4,%5,%6,%7}, {%8,%9}, {%0,%1,%2,%3};"
        : "+f"(d[0]), "+f"(d[1]), "+f"(d[2]), "+f"(d[3])
        : "r"(a[0]), "r"(a[1]), "r"(a[2]), "r"(a[3]), "r"(b0), "r"(b1));
}
// fp16 data, f16 accum
__device__ __forceinline__ void mma16hh(uint32_t* d, const uint32_t* a, uint32_t b0, uint32_t b1) {
    asm volatile(
        "mma.sync.aligned.m16n8k16.row.col.f16.f16.f16.f16 "
        "{%0,%1}, {%2,%3,%4,%5}, {%6,%7}, {%0,%1};"
        : "+r"(d[0]), "+r"(d[1])
        : "r"(a[0]), "r"(a[1]), "r"(a[2]), "r"(a[3]), "r"(b0), "r"(b1));
}
__device__ __forceinline__ float fexp(float x) {
    x = fmaxf(x, -87.0f);
    float t = fmaf(x, 1.4426950408889634f, 12582912.0f);
    float i = t - 12582912.0f;
    float f = fmaf(x, 1.4426950408889634f, -i);
    float y = f * 0.6931471805599453f;
    float p = fmaf(y, 0.0083333338f, 0.041666668f);
    p = fmaf(y, p, 0.16666667f);
    p = fmaf(y, p, 0.5f);
    p = fmaf(y, p, 1.0f);
    p = fmaf(y, p, 1.0f);
    return p * __int_as_float(((int)i + 127) << 23);
}
__device__ __forceinline__ void split2h(float v, __half& h, __half& l) {
    h = __float2half(v);
    l = __float2half((v - __half2float(h)) * 256.0f);
}

// ---------------------------------------------------------------------------
// Implicit-im2col conv GEMM, fp16 hi/lo, single-sync 3-stage mainloop.
// BM=128, BN=128, BK=32, occ 2. W stored compact [h | l].
// Phases: blk0 = Wh*xl (f16 acc), blk1 = Wl*xh (f16 acc), blk2 = Wh*xh (f32).
// ---------------------------------------------------------------------------
#define CSTAGE (2*128*STR)
#define GSMEM_C (3*CSTAGE)

template <int TAPS>
__global__ __launch_bounds__(256, 2) void gemm_conv(
    const __half* __restrict__ W, float* __restrict__ C,
    const float* __restrict__ bias, int ptype)
{
    extern __shared__ char sm_[];
    uint32_t smb = smem_u32(sm_);
    int tid = threadIdx.x, lane = tid & 31, wid = tid >> 5;
    int wm = wid & 1, wn = wid >> 1;
    int b = blockIdx.z;
    int m0 = blockIdx.y * 128, n0 = blockIdx.x * 128;
    const int KB = TAPS * 256;
    const int Kp2 = 2 * KB;        // compact row length
    const int nk = TAPS * 24;
    const int nkc = TAPS * 16;
    const __half* XH = g_xt_h + (size_t)b * 4356 * 256;
    const __half* XL = g_xt_l + (size_t)b * 4356 * 256;
    const __half* Wb = W + (size_t)m0 * Kp2;

    auto load = [&](int kt) {
        int st = kt % 3;
        uint32_t as = smb + st * CSTAGE;
        uint32_t bs = smb + st * CSTAGE + 128 * STR;
        int blk = kt / (TAPS * 8);
        int rem = kt - blk * (TAPS * 8);
        int t = rem >> 3, c0 = (rem & 7) << 5;
        int dy = (TAPS == 9) ? t / 3 : 1;
        int dx = (TAPS == 9) ? t % 3 : 1;
        int offA = ((blk == 1) ? KB : 0) + rem * 32;    // blk1 reads W-lo block
        const __half* buf = (blk == 0) ? XL : XH;        // blk0 pairs Wh with xl
#pragma unroll
        for (int u = 0; u < 2; u++) {
            int e = tid + u * 256;
            int row = e >> 2, ch = e & 3;
            cpa16(as + row * STR + ch * 16, Wb + (size_t)row * Kp2 + offA + ch * 8);
        }
#pragma unroll
        for (int u = 0; u < 2; u++) {
            int e = tid + u * 256;
            int row = e >> 2, ch = e & 3;
            int p = n0 + row, y = p >> 6, xx = p & 63;
            cpa16(bs + row * STR + ch * 16,
                  buf + (size_t)((y + dy) * 66 + (xx + dx)) * 256 + c0 + ch * 8);
        }
        asm volatile("cp.async.commit_group;" ::: "memory");
    };

    uint32_t acch[4][4][2];
#pragma unroll
    for (int i = 0; i < 4; i++)
#pragma unroll
        for (int j = 0; j < 4; j++) { acch[i][j][0] = 0u; acch[i][j][1] = 0u; }

    load(0);
    load(1);
    // phase 1: cross terms, f16 accumulator (single sync, early prefetch)
    for (int kt = 0; kt < nkc; kt++) {
        asm volatile("cp.async.wait_group 1;" ::: "memory");
        __syncthreads();
        if (kt + 2 < nk) load(kt + 2);
        else asm volatile("cp.async.commit_group;" ::: "memory");
        int st = kt % 3;
        uint32_t as = smb + st * CSTAGE + (wm * 64 + (lane & 15)) * STR + (lane >> 4) * 16;
        uint32_t bs = smb + st * CSTAGE + 128 * STR + (wn * 32 + (lane & 15)) * STR + (lane >> 4) * 16;
#pragma unroll
        for (int kk = 0; kk < 2; kk++) {
            uint32_t a[4][4], bb[2][4];
#pragma unroll
            for (int mt = 0; mt < 4; mt++) ldm4(a[mt], as + mt * 16 * STR + kk * 32);
#pragma unroll
            for (int nt = 0; nt < 2; nt++) ldm4(bb[nt], bs + nt * 16 * STR + kk * 32);
#pragma unroll
            for (int mt = 0; mt < 4; mt++)
#pragma unroll
                for (int n8 = 0; n8 < 4; n8++)
                    mma16hh(acch[mt][n8], a[mt], bb[n8 >> 1][n8 & 1], bb[n8 >> 1][(n8 & 1) + 2]);
        }
    }
    // fold cross terms (scaled 1/256) into f32 accumulator
    float accf[4][4][4];
#pragma unroll
    for (int mt = 0; mt < 4; mt++)
#pragma unroll
        for (int n8 = 0; n8 < 4; n8++) {
            float2 c0 = __half22float2(*(__half2*)&acch[mt][n8][0]);
            float2 c1 = __half22float2(*(__half2*)&acch[mt][n8][1]);
            accf[mt][n8][0] = c0.x * ISC;
            accf[mt][n8][1] = c0.y * ISC;
            accf[mt][n8][2] = c1.x * ISC;
            accf[mt][n8][3] = c1.y * ISC;
        }
    // phase 2: main term, f32 accumulator
    for (int kt = nkc; kt < nk; kt++) {
        asm volatile("cp.async.wait_group 1;" ::: "memory");
        __syncthreads();
        if (kt + 2 < nk) load(kt + 2);
        else asm volatile("cp.async.commit_group;" ::: "memory");
        int st = kt % 3;
        uint32_t as = smb + st * CSTAGE + (wm * 64 + (lane & 15)) * STR + (lane >> 4) * 16;
        uint32_t bs = smb + st * CSTAGE + 128 * STR + (wn * 32 + (lane & 15)) * STR + (lane >> 4) * 16;
#pragma unroll
        for (int kk = 0; kk < 2; kk++) {
            uint32_t a[4][4], bb[2][4];
#pragma unroll
            for (int mt = 0; mt < 4; mt++) ldm4(a[mt], as + mt * 16 * STR + kk * 32);
#pragma unroll
            for (int nt = 0; nt < 2; nt++) ldm4(bb[nt], bs + nt * 16 * STR + kk * 32);
#pragma unroll
            for (int mt = 0; mt < 4; mt++)
#pragma unroll
                for (int n8 = 0; n8 < 4; n8++)
                    mma16h(accf[mt][n8], a[mt], bb[n8 >> 1][n8 & 1], bb[n8 >> 1][(n8 & 1) + 2]);
        }
    }

    float* Cb = C + (size_t)b * NC * NPIX;
    float s1a[8], s2a[8];
#pragma unroll
    for (int i = 0; i < 8; i++) { s1a[i] = 0.f; s2a[i] = 0.f; }
#pragma unroll
    for (int mt = 0; mt < 4; mt++) {
        int row = m0 + wm * 64 + mt * 16 + (lane >> 2);
        float bi0 = bias[row], bi1 = bias[row + 8];
#pragma unroll
        for (int n8 = 0; n8 < 4; n8++) {
            int col = n0 + wn * 32 + n8 * 8 + (lane & 3) * 2;
            float2 v0, v1;
            v0.x = accf[mt][n8][0] + bi0; v0.y = accf[mt][n8][1] + bi0;
            v1.x = accf[mt][n8][2] + bi1; v1.y = accf[mt][n8][3] + bi1;
            *(float2*)&Cb[(size_t)row * 4096 + col] = v0;
            *(float2*)&Cb[(size_t)(row + 8) * 4096 + col] = v1;
            s1a[mt * 2 + 0] += v0.x + v0.y;
            s2a[mt * 2 + 0] += v0.x * v0.x + v0.y * v0.y;
            s1a[mt * 2 + 1] += v1.x + v1.y;
            s2a[mt * 2 + 1] += v1.x * v1.x + v1.y * v1.y;
        }
    }
#pragma unroll
    for (int i = 0; i < 8; i++) {
        s1a[i] += __shfl_xor_sync(0xFFFFFFFF, s1a[i], 1);
        s1a[i] += __shfl_xor_sync(0xFFFFFFFF, s1a[i], 2);
        s2a[i] += __shfl_xor_sync(0xFFFFFFFF, s2a[i], 1);
        s2a[i] += __shfl_xor_sync(0xFFFFFFFF, s2a[i], 2);
    }
    __syncthreads();
    float* smr = (float*)sm_;
    if ((lane & 3) == 0) {
#pragma unroll
        for (int mt = 0; mt < 4; mt++)
#pragma unroll
            for (int h = 0; h < 2; h++) {
                int r = wm * 64 + mt * 16 + h * 8 + (lane >> 2);
                smr[r * 4 + wn] = s1a[mt * 2 + h];
                smr[512 + r * 4 + wn] = s2a[mt * 2 + h];
            }
    }
    __syncthreads();
    if (tid < 128) {
        float a1 = smr[tid * 4] + smr[tid * 4 + 1] + smr[tid * 4 + 2] + smr[tid * 4 + 3];
        float a2 = smr[512 + tid * 4] + smr[512 + tid * 4 + 1]
                 + smr[512 + tid * 4 + 2] + smr[512 + tid * 4 + 3];
        int slot = b * 32 + blockIdx.x;
        g_psum1[(ptype * 128 + slot) * 256 + m0 + tid] = a1;
        g_psum2[(ptype * 128 + slot) * 256 + m0 + tid] = a2;
    }
}

// ---------------------------------------------------------------------------
// S GEMM fp16 hi/lo compact [h|l], single-sync 3-stage. BM=BN=128, occ 2.
// Phases: blk0 = Qh*Kl, blk1 = Ql*Kh (f16 acc), blk2 = Qh*Kh (f32 acc).
// ---------------------------------------------------------------------------
#define SSTAGE (128*STR)
#define GSMEM_S (6*SSTAGE)

__global__ __launch_bounds__(256, 2) void gemm_s(
    const __half* __restrict__ A, const __half* __restrict__ B)
{
    extern __shared__ char sm_[];
    uint32_t smb = smem_u32(sm_);
    int tid = threadIdx.x, lane = tid & 31, wid = tid >> 5;
    int wm = wid & 1, wn = wid >> 1;
    int bz = blockIdx.z;
    int m0 = blockIdx.y * 128, n0 = blockIdx.x * 128;
    const __half* Ab = A + (size_t)bz * 4096 * 512 + (size_t)m0 * 512;
    const __half* Bb = B + (size_t)bz * 4096 * 512 + (size_t)n0 * 512;
    const int nk = 24, nkc = 16;

    auto load = [&](int kt) {
        int st = kt % 3;
        uint32_t as = smb + st * SSTAGE;
        uint32_t bs = smb + 3 * SSTAGE + st * SSTAGE;
        int blk = kt >> 3;
        int k0 = (kt & 7) * 32;
        int offA = ((blk == 1) ? 256 : 0) + k0;   // blk1: Q-lo
        int offB = ((blk == 0) ? 256 : 0) + k0;   // blk0: K-lo
#pragma unroll
        for (int i = 0; i < 2; i++) {
            int e = tid + i * 256;
            int row = e >> 2, ch = e & 3;
            cpa16(as + row * STR + ch * 16, Ab + (size_t)row * 512 + offA + ch * 8);
            cpa16(bs + row * STR + ch * 16, Bb + (size_t)row * 512 + offB + ch * 8);
        }
        asm volatile("cp.async.commit_group;" ::: "memory");
    };

    uint32_t acch[4][4][2];
#pragma unroll
    for (int i = 0; i < 4; i++)
#pragma unroll
        for (int j = 0; j < 4; j++) { acch[i][j][0] = 0u; acch[i][j][1] = 0u; }

    load(0);
    load(1);
    for (int kt = 0; kt < nkc; kt++) {
        asm volatile("cp.async.wait_group 1;" ::: "memory");
        __syncthreads();
        if (kt + 2 < nk) load(kt + 2);
        else asm volatile("cp.async.commit_group;" ::: "memory");
        int st = kt % 3;
        uint32_t as = smb + st * SSTAGE + (wm * 64 + (lane & 15)) * STR + (lane >> 4) * 16;
        uint32_t bs = smb + 3 * SSTAGE + st * SSTAGE + (wn * 32 + (lane & 15)) * STR + (lane >> 4) * 16;
#pragma unroll
        for (int kk = 0; kk < 2; kk++) {
            uint32_t a[4][4], bb[2][4];
#pragma unroll
            for (int mt = 0; mt < 4; mt++) ldm4(a[mt], as + mt * 16 * STR + kk * 32);
#pragma unroll
            for (int nt = 0; nt < 2; nt++) ldm4(bb[nt], bs + nt * 16 * STR + kk * 32);
#pragma unroll
            for (int mt = 0; mt < 4; mt++)
#pragma unroll
                for (int n8 = 0; n8 < 4; n8++)
                    mma16hh(acch[mt][n8], a[mt], bb[n8 >> 1][n8 & 1], bb[n8 >> 1][(n8 & 1) + 2]);
        }
    }
    float accf[4][4][4];
#pragma unroll
    for (int mt = 0; mt < 4; mt++)
#pragma unroll
        for (int n8 = 0; n8 < 4; n8++) {
            float2 c0 = __half22float2(*(__half2*)&acch[mt][n8][0]);
            float2 c1 = __half22float2(*(__half2*)&acch[mt][n8][1]);
            accf[mt][n8][0] = c0.x * ISC;
            accf[mt][n8][1] = c0.y * ISC;
            accf[mt][n8][2] = c1.x * ISC;
            accf[mt][n8][3] = c1.y * ISC;
        }
    for (int kt = nkc; kt < nk; kt++) {
        asm volatile("cp.async.wait_group 1;" ::: "memory");
        __syncthreads();
        if (kt + 2 < nk) load(kt + 2);
        else asm volatile("cp.async.commit_group;" ::: "memory");
        int st = kt % 3;
        uint32_t as = smb + st * SSTAGE + (wm * 64 + (lane & 15)) * STR + (lane >> 4) * 16;
        uint32_t bs = smb + 3 * SSTAGE + st * SSTAGE + (wn * 32 + (lane & 15)) * STR + (lane >> 4) * 16;
#pragma unroll
        for (int kk = 0; kk < 2; kk++) {
            uint32_t a[4][4], bb[2][4];
#pragma unroll
            for (int mt = 0; mt < 4; mt++) ldm4(a[mt], as + mt * 16 * STR + kk * 32);
#pragma unroll
            for (int nt = 0; nt < 2; nt++) ldm4(bb[nt], bs + nt * 16 * STR + kk * 32);
#pragma unroll
            for (int mt = 0; mt < 4; mt++)
#pragma unroll
                for (int n8 = 0; n8 < 4; n8++)
                    mma16h(accf[mt][n8], a[mt], bb[n8 >> 1][n8 & 1], bb[n8 >> 1][(n8 & 1) + 2]);
        }
    }

    // epilogue: per-warp 32-k group max -> exp -> fp16 P, partial (m, sum)
    __half* Pb = g_P16 + (size_t)bz * 4096 * 4096;
    int g = blockIdx.x * 4 + wn;
#pragma unroll
    for (int mt = 0; mt < 4; mt++) {
#pragma unroll
        for (int h = 0; h < 2; h++) {
            float m = -3.4e38f;
#pragma unroll
            for (int n8 = 0; n8 < 4; n8++)
                m = fmaxf(m, fmaxf(accf[mt][n8][2 * h], accf[mt][n8][2 * h + 1]));
            m = fmaxf(m, __shfl_xor_sync(0xFFFFFFFF, m, 1));
            m = fmaxf(m, __shfl_xor_sync(0xFFFFFFFF, m, 2));
            int row = m0 + wm * 64 + mt * 16 + h * 8 + (lane >> 2);
            float s = 0.f;
#pragma unroll
            for (int n8 = 0; n8 < 4; n8++) {
                float e0 = fexp(accf[mt][n8][2 * h] - m);
                float e1 = fexp(accf[mt][n8][2 * h + 1] - m);
                s += e0 + e1;
                int col = n0 + wn * 32 + n8 * 8 + (lane & 3) * 2;
                *(__half2*)&Pb[(size_t)row * 4096 + col] = __floats2half2_rn(e0, e1);
            }
            s += __shfl_xor_sync(0xFFFFFFFF, s, 1);
            s += __shfl_xor_sync(0xFFFFFFFF, s, 2);
            if ((lane & 3) == 0) {
                size_t o = ((size_t)bz * 128 + g) * 4096 + row;
                g_pm[o] = m;
                g_ps[o] = s;
            }
        }
    }
}

// combine 128 group partials + border key (8 sbp partials) -> m, 1/Z, bw
__global__ void sm_combine() {
    int i = blockIdx.x * 256 + threadIdx.x;
    int b = i >> 12, q = i & 4095;
    float sbv = 0.f;
#pragma unroll
    for (int j = 0; j < 8; j++) sbv += g_sbp[j * (NB * NPIX) + i];
    float mg = sbv;
#pragma unroll 8
    for (int t = 0; t < 128; t++)
        mg = fmaxf(mg, g_pm[((size_t)b * 128 + t) * 4096 + q]);
    float Z = 260.f * fexp(sbv - mg);
    float eb = Z;
#pragma unroll 8
    for (int t = 0; t < 128; t++) {
        size_t o = ((size_t)b * 128 + t) * 4096 + q;
        Z += fexp(g_pm[o] - mg) * g_ps[o];
    }
    float iz = 1.f / Z;
    g_m[i] = mg;
    g_iz[i] = iz;
    g_bw[i] = eb * iz;
}

// ---------------------------------------------------------------------------
// Fused O GEMM (fp16 data, f32 acc) — R12 form (two-sync, in-iter B fill).
// BM=256, BN=64, BK=32, occ 2.
// ---------------------------------------------------------------------------
#define OASTG (256*STR)
#define OB0   (3*OASTG)
#define OBSTG (64*STR)
#define GSMEM_O (OB0 + 2*OBSTG)

__global__ __launch_bounds__(256, 2) void gemm_o(float* __restrict__ Cout)
{
    extern __shared__ char sm_[];
    uint32_t smb = smem_u32(sm_);
    int tid = threadIdx.x, lane = tid & 31, wid = tid >> 5;
    int wm = wid >> 1, wn = wid & 1;
    int b = blockIdx.z;
    int n0 = blockIdx.x * 64;
    const __half* Vb = g_vf + (size_t)b * NC * NPIX;
    const int nk = 128;

    int fq = tid >> 2, fqt = tid & 3;
    int q = n0 + fq;
    float mq = g_m[b * 4096 + q];
    float izq = g_iz[b * 4096 + q];
    const __half* Pq = g_P16 + ((size_t)b * 4096 + q) * 4096 + fqt * 8;
    const float* pmq = g_pm + (size_t)b * 128 * 4096 + q;

    auto loadA = [&](int kt) {
        int st = kt % 3;
#pragma unroll
        for (int u = 0; u < 4; u++) {
            int e = tid + u * 256;
            int row = e >> 2, ch = e & 3;
            cpa16(smb + st * OASTG + row * STR + ch * 16,
                  Vb + (size_t)row * 4096 + kt * 32 + ch * 8);
        }
        asm volatile("cp.async.commit_group;" ::: "memory");
    };

    float acc[4][4][4];
#pragma unroll
    for (int i = 0; i < 4; i++)
#pragma unroll
        for (int j = 0; j < 4; j++)
#pragma unroll
            for (int r = 0; r < 4; r++) acc[i][j][r] = 0.f;

    uint4 pf;
    float pmv;
    loadA(0);
    loadA(1);
    pf = *(const uint4*)Pq;
    pmv = pmq[0];

    for (int kt = 0; kt < nk; kt++) {
        asm volatile("cp.async.wait_group 1;" ::: "memory");
        __syncthreads();
        {
            float sc = fexp(pmv - mq) * izq;
            __half2 s2 = __float2half2_rn(sc);
            __half2* ph = (__half2*)&pf;
            uint4 o;
            __half2* oh = (__half2*)&o;
            oh[0] = __hmul2(ph[0], s2);
            oh[1] = __hmul2(ph[1], s2);
            oh[2] = __hmul2(ph[2], s2);
            oh[3] = __hmul2(ph[3], s2);
            *(uint4*)(sm_ + OB0 + (kt & 1) * OBSTG + fq * STR + fqt * 16) = o;
        }
        if (kt + 1 < nk) {
            pf = *(const uint4*)(Pq + (kt + 1) * 32);
            pmv = pmq[(size_t)(kt + 1) * 4096];
        }
        if (kt + 2 < nk) loadA(kt + 2);
        else asm volatile("cp.async.commit_group;" ::: "memory");
        __syncthreads();

        int st = kt % 3, b2 = kt & 1;
        uint32_t as_ = smb + st * OASTG + (wm * 64 + (lane & 15)) * STR + (lane >> 4) * 16;
        uint32_t bs_ = smb + OB0 + b2 * OBSTG + (wn * 32 + (lane & 15)) * STR + (lane >> 4) * 16;
#pragma unroll
        for (int kk = 0; kk < 2; kk++) {
            uint32_t a[4][4], bb[2][4];
#pragma unroll
            for (int mt = 0; mt < 4; mt++) ldm4(a[mt], as_ + mt * 16 * STR + kk * 32);
#pragma unroll
            for (int nt = 0; nt < 2; nt++) ldm4(bb[nt], bs_ + nt * 16 * STR + kk * 32);
#pragma unroll
            for (int mt = 0; mt < 4; mt++)
#pragma unroll
                for (int n8 = 0; n8 < 4; n8++)
                    mma16h(acc[mt][n8], a[mt], bb[n8 >> 1][n8 & 1], bb[n8 >> 1][(n8 & 1) + 2]);
        }
    }

    float* Cb = Cout + (size_t)b * NC * NPIX;
    const float* bwp = g_bw + (size_t)b * 4096;
#pragma unroll
    for (int mt = 0; mt < 4; mt++) {
        int row = wm * 64 + mt * 16 + (lane >> 2);
        float vb0 = g_vbv[row], vb1 = g_vbv[row + 8];
#pragma unroll
        for (int n8 = 0; n8 < 4; n8++) {
            int col = n0 + wn * 32 + n8 * 8 + (lane & 3) * 2;
            float w0 = bwp[col], w1 = bwp[col + 1];
            float2 v0, v1;
            v0.x = fmaf(w0, vb0, acc[mt][n8][0]); v0.y = fmaf(w1, vb0, acc[mt][n8][1]);
            v1.x = fmaf(w0, vb1, acc[mt][n8][2]); v1.y = fmaf(w1, vb1, acc[mt][n8][3]);
            *(float2*)&Cb[(size_t)row * 4096 + col] = v0;
            *(float2*)&Cb[(size_t)(row + 8) * 4096 + col] = v1;
        }
    }
}

// ---- prep kernels ----
// zero only the 260 border positions of each 66x66 grid (both buffers)
__global__ void zero_border() {
    int idx = blockIdx.x * 256 + threadIdx.x;    // NB*260*32 uint4 slots
    if (idx >= NB * 260 * 32) return;
    int u = idx & 31;
    int pi = (idx >> 5) % 260;
    int b = idx / (260 * 32);
    int y, x;
    if (pi < 66)       { y = 0;  x = pi; }
    else if (pi < 132) { y = 65; x = pi - 66; }
    else if (pi < 196) { y = pi - 132 + 1; x = 0; }
    else               { y = pi - 196 + 1; x = 65; }
    size_t o = ((size_t)b * 4356 + y * 66 + x) * 32 + u;
    ((uint4*)g_xt_h)[o] = make_uint4(0, 0, 0, 0);
    ((uint4*)g_xt_l)[o] = make_uint4(0, 0, 0, 0);
}

__global__ void xt_fill(const float* __restrict__ x) {
    __shared__ float tile[32][33];
    int b = blockIdx.z;
    int p0 = blockIdx.x * 32, c0 = blockIdx.y * 32;
    int tx = threadIdx.x, ty = threadIdx.y;
    const float* s = x + (size_t)b * NC * NPIX;
    for (int j = 0; j < 32; j += 8)
        tile[ty + j][tx] = s[(size_t)(c0 + ty + j) * NPIX + p0 + tx];
    __syncthreads();
    for (int j = 0; j < 32; j += 8) {
        int p = p0 + ty + j, y = p >> 6, xx = p & 63;
        size_t o = ((size_t)b * 4356 + (y + 1) * 66 + (xx + 1)) * 256 + c0 + tx;
        __half h, l;
        split2h(tile[tx][ty + j], h, l);
        g_xt_h[o] = h;
        g_xt_l[o] = l;
    }
}

// Wq compact [h | l*256], k ordering t*256+c within block
__global__ void wsplit_q(const float* __restrict__ w) {
    int idx = blockIdx.x * 256 + threadIdx.x;
    if (idx >= NC * 2304) return;
    int m = idx / 2304, r = idx % 2304;
    int c = r / 9, t = r % 9;
    __half h, l;
    split2h(w[idx], h, l);
    size_t base = (size_t)m * 4608 + t * 256 + c;
    g_wqh[base] = h;
    g_wqh[base + 2304] = l;
}

__global__ void wsplit1(const float* __restrict__ w, __half* __restrict__ o) {
    int idx = blockIdx.x * 256 + threadIdx.x;
    if (idx >= NC * NC) return;
    int m = idx / NC, c = idx % NC;
    __half h, l;
    split2h(w[idx], h, l);
    size_t base = (size_t)m * 512 + c;
    o[base] = h;
    o[base + 256] = l;
}

// transpose [c][pix] -> [pix][h|l] with affine; Q path also emits border partials
__global__ void tsplit(const float* __restrict__ src, __half* __restrict__ dst,
                       const float* __restrict__ aa, const float* __restrict__ ad,
                       const float* __restrict__ kbv, float* __restrict__ sbp) {
    __shared__ float tile[32][33];
    __shared__ float sbred[8][32];
    int b = blockIdx.z;
    int p0 = blockIdx.x * 32, c0 = blockIdx.y * 32;
    int tx = threadIdx.x, ty = threadIdx.y;
    const float* s = src + (size_t)b * NC * NPIX;
    for (int j = 0; j < 32; j += 8) {
        float a = aa[c0 + ty + j], d = ad[c0 + ty + j];
        tile[ty + j][tx] = fmaf(a, s[(size_t)(c0 + ty + j) * NPIX + p0 + tx], d);
    }
    __syncthreads();
    for (int j = 0; j < 32; j += 8) {
        __half h, l;
        split2h(tile[tx][ty + j], h, l);
        __half* o = dst + ((size_t)b * 4096 + p0 + ty + j) * 512 + c0 + tx;
        o[0] = h;
        o[256] = l;
    }
    if (kbv) {
        float part = 0.f;
#pragma unroll
        for (int c = ty; c < 32; c += 8)
            part = fmaf(kbv[c0 + c], tile[c][tx], part);
        sbred[ty][tx] = part;
        __syncthreads();
        if (ty == 0) {
            float sum = 0.f;
#pragma unroll
            for (int j = 0; j < 8; j++) sum += sbred[j][tx];
            sbp[(size_t)blockIdx.y * (NB * NPIX) + b * NPIX + p0 + tx] = sum;
        }
    }
}

__global__ void vf_k() {
    size_t i4 = (size_t)blockIdx.x * 256 + threadIdx.x;
    size_t e = i4 * 4;
    int c = (int)((e >> 12) & 255);
    float a = g_a[512 + c], d = g_dd[512 + c];
    float4 v = *(float4*)(g_vc + e);
    __half h[4];
    h[0] = __float2half(fmaf(a, v.x, d));
    h[1] = __float2half(fmaf(a, v.y, d));
    h[2] = __float2half(fmaf(a, v.z, d));
    h[3] = __float2half(fmaf(a, v.w, d));
    *(uint2*)(g_vf + e) = *(uint2*)h;
}

// tiny stats: sum 128 conv partials per channel
__global__ void stats_k(const float* __restrict__ bq, const float* __restrict__ gq, const float* __restrict__ betaq,
                        const float* __restrict__ bk, const float* __restrict__ gk, const float* __restrict__ betak,
                        const float* __restrict__ bv, const float* __restrict__ gv, const float* __restrict__ betav)
{
    int t = blockIdx.x;
    int c = threadIdx.x;
    float S1f = 0.f, S2f = 0.f;
    for (int j = 0; j < 128; j++) {
        S1f += g_psum1[(t * 128 + j) * 256 + c];
        S2f += g_psum2[(t * 128 + j) * 256 + c];
    }
    double S1 = S1f, S2 = S2f, cnt = 16384.0;
    float bias = (t == 0) ? bq[c] : (t == 1) ? bk[c] : bv[c];
    float g    = (t == 0) ? gq[c] : (t == 1) ? gk[c] : gv[c];
    float be   = (t == 0) ? betaq[c] : (t == 1) ? betak[c] : betav[c];
    if (t > 0) {
        cnt = 17424.0;
        S1 += 1040.0 * (double)bias;
        S2 += 1040.0 * (double)bias * (double)bias;
    }
    double mean = S1 / cnt;
    double var = S2 / cnt - mean * mean;
    float a = g * rsqrtf((float)var + 1e-5f);
    float d = be - a * (float)mean;
    g_a[t * NC + c] = a;
    g_dd[t * NC + c] = d;
    if (t == 1) g_kbv[c] = fmaf(a, bias, d);
    if (t == 2) g_vbv[c] = fmaf(a, bias, d);
}

// ---------------------------------------------------------------------------
extern "C" void kernel_launch(void* const* d_in, const int* in_sizes, int n_in,
                              void* d_out, int out_size)
{
    const float* x     = (const float*)d_in[0];
    const float* Wq    = (const float*)d_in[1];
    const float* bq    = (const float*)d_in[2];
    const float* gq    = (const float*)d_in[3];
    const float* betaq = (const float*)d_in[4];
    const float* Wk    = (const float*)d_in[5];
    const float* bk    = (const float*)d_in[6];
    const float* gk    = (const float*)d_in[7];
    const float* betak = (const float*)d_in[8];
    const float* Wv    = (const float*)d_in[9];
    const float* bv    = (const float*)d_in[10];
    const float* gv    = (const float*)d_in[11];
    const float* betav = (const float*)d_in[12];
    float* out = (float*)d_out;

    cudaFuncSetAttribute(gemm_conv<9>, cudaFuncAttributeMaxDynamicSharedMemorySize, GSMEM_C);
    cudaFuncSetAttribute(gemm_conv<1>, cudaFuncAttributeMaxDynamicSharedMemorySize, GSMEM_C);
    cudaFuncSetAttribute(gemm_s, cudaFuncAttributeMaxDynamicSharedMemorySize, GSMEM_S);
    cudaFuncSetAttribute(gemm_o, cudaFuncAttributeMaxDynamicSharedMemorySize, GSMEM_O);

    __half *p_wkh, *p_wvh, *p_qth, *p_kth;
    float *p_qc, *p_kc, *p_vc, *p_a, *p_dd, *p_kbv, *p_sbp;
    cudaGetSymbolAddress((void**)&p_wkh, g_wkh);
    cudaGetSymbolAddress((void**)&p_wvh, g_wvh);
    cudaGetSymbolAddress((void**)&p_qth, g_qth);
    cudaGetSymbolAddress((void**)&p_kth, g_kth);
    cudaGetSymbolAddress((void**)&p_qc,  g_qc);
    cudaGetSymbolAddress((void**)&p_kc,  g_kc);
    cudaGetSymbolAddress((void**)&p_vc,  g_vc);
    cudaGetSymbolAddress((void**)&p_a,   g_a);
    cudaGetSymbolAddress((void**)&p_dd,  g_dd);
    cudaGetSymbolAddress((void**)&p_kbv, g_kbv);
    cudaGetSymbolAddress((void**)&p_sbp, g_sbp);
    __half *p_wqh;
    cudaGetSymbolAddress((void**)&p_wqh, g_wqh);

    // 1. border zero + padded transposed hi/lo x (fp16) + weight splits
    zero_border<<<(NB * 260 * 32 + 255) / 256, 256>>>();
    xt_fill<<<dim3(128, 8, NB), dim3(32, 8)>>>(x);
    wsplit_q<<<(NC * 2304 + 255) / 256, 256>>>(Wq);
    wsplit1<<<(NC * NC + 255) / 256, 256>>>(Wk, p_wkh);
    wsplit1<<<(NC * NC + 255) / 256, 256>>>(Wv, p_wvh);

    // 2. convs (implicit im2col, fp16 hi/lo compact, mixed-acc, single-sync)
    gemm_conv<9><<<dim3(32, 2, NB), 256, GSMEM_C>>>(p_wqh, p_qc, bq, 0);
    gemm_conv<1><<<dim3(32, 2, NB), 256, GSMEM_C>>>(p_wkh, p_kc, bk, 1);
    gemm_conv<1><<<dim3(32, 2, NB), 256, GSMEM_C>>>(p_wvh, p_vc, bv, 2);

    // 3. BN stats (tiny) + splits (Q path emits border partials) + V fp16
    stats_k<<<3, 256>>>(bq, gq, betaq, bk, gk, betak, bv, gv, betav);
    tsplit<<<dim3(128, 8, NB), dim3(32, 8)>>>(p_qc, p_qth, p_a, p_dd, p_kbv, p_sbp);
    tsplit<<<dim3(128, 8, NB), dim3(32, 8)>>>(p_kc, p_kth, p_a + 256, p_dd + 256, 0, 0);
    vf_k<<<(int)(((size_t)NB * NC * NPIX / 4) / 256), 256>>>();

    // 4. S GEMM (compact [h|l], mixed-acc, single-sync) -> fp16 exp-tiles + partials
    gemm_s<<<dim3(32, 32, NB), 256, GSMEM_S>>>(p_qth, p_kth);

    // 5. combine partials -> m, 1/Z, bw
    sm_combine<<<64, 256>>>();

    // 6. fused O GEMM (fp16, f32 acc, occ 2)
    gemm_o<<<dim3(64, 1, NB), 256, GSMEM_O>>>(out);
}

// round 15
// speedup vs baseline: 1.5329x; 1.5329x over previous
#include <cuda_runtime.h>
#include <cuda_fp16.h>
#include <math.h>
#include <stdint.h>

#define NB 4
#define NC 256
#define NPIX 4096
#define STR 80
#define ISC (1.0f/256.0f)

// ---- static device scratch ----
__device__ __half g_xt_h[(size_t)NB*4356*256];   // padded x fp16 hi, [b][pix66][c]
__device__ __half g_xt_l[(size_t)NB*4356*256];   // (x-hi)*256
__device__ __half g_wqh[NC*6912];                // Wq blocks [h | l*256 | h], k=t*256+c
__device__ __half g_wkh[NC*768];
__device__ __half g_wvh[NC*768];
__device__ float g_qc[(size_t)NB*NC*NPIX];
__device__ float g_kc[(size_t)NB*NC*NPIX];
__device__ float g_vc[(size_t)NB*NC*NPIX];
__device__ __half g_qth[(size_t)NB*NPIX*768];    // BN(Q)^T blocks [h | l | h]
__device__ __half g_kth[(size_t)NB*NPIX*768];    // BN(K)^T blocks [l | h | h]
__device__ __half g_vf[(size_t)NB*NC*NPIX];      // BN(V) fp16 [b][c][k]
__device__ __half g_P16[(size_t)NB*NPIX*NPIX];   // exp(s-lm) fp16 [b][q][k]
__device__ float g_pm[(size_t)NB*128*NPIX];      // per-32k-group max
__device__ float g_ps[(size_t)NB*128*NPIX];      // per-32k-group sum
__device__ float g_psum1[3*128*256];             // conv partial sums [t][slot][ch]
__device__ float g_psum2[3*128*256];
__device__ float g_sbp[8*NB*NPIX];               // border-score partials [cblk][b*q]
__device__ float g_bw[NB*NPIX];
__device__ float g_m[NB*NPIX];
__device__ float g_iz[NB*NPIX];
__device__ float g_a[3*NC];
__device__ float g_dd[3*NC];
__device__ float g_kbv[NC];
__device__ float g_vbv[NC];

// ---- helpers ----
__device__ __forceinline__ uint32_t smem_u32(const void* p) {
    uint32_t a;
    asm("{ .reg .u64 t; cvta.to.shared.u64 t, %1; cvt.u32.u64 %0, t; }" : "=r"(a) : "l"(p));
    return a;
}
__device__ __forceinline__ void cpa16(uint32_t s, const void* g) {
    asm volatile("cp.async.cg.shared.global [%0], [%1], 16;" :: "r"(s), "l"(g));
}
__device__ __forceinline__ void ldm4(uint32_t* r, uint32_t addr) {
    asm volatile("ldmatrix.sync.aligned.m8n8.x4.shared.b16 {%0,%1,%2,%3}, [%4];"
                 : "=r"(r[0]), "=r"(r[1]), "=r"(r[2]), "=r"(r[3]) : "r"(addr));
}
// fp16 data, f32 accum
__device__ __forceinline__ void mma16h(float* d, const uint32_t* a, uint32_t b0, uint32_t b1) {
    asm volatile(
        "mma.sync.aligned.m16n8k16.row.col.f32.f16.f16.f32 "
        "{%0,%1,%2,%3}, {%4,%5,%6,%7}, {%8,%9}, {%0,%1,%2,%3};"
        : "+f"(d[0]), "+f"(d[1]), "+f"(d[2]), "+f"(d[3])
        : "r"(a[0]), "r"(a[1]), "r"(a[2]), "r"(a[3]), "r"(b0), "r"(b1));
}
// fp16 data, f16 accum
__device__ __forceinline__ void mma16hh(uint32_t* d, const uint32_t* a, uint32_t b0, uint32_t b1) {
    asm volatile(
        "mma.sync.aligned.m16n8k16.row.col.f16.f16.f16.f16 "
        "{%0,%1}, {%2,%3,%4,%5}, {%6,%7}, {%0,%1};"
        : "+r"(d[0]), "+r"(d[1])
        : "r"(a[0]), "r"(a[1]), "r"(a[2]), "r"(a[3]), "r"(b0), "r"(b1));
}
__device__ __forceinline__ float fexp(float x) {
    x = fmaxf(x, -87.0f);
    float t = fmaf(x, 1.4426950408889634f, 12582912.0f);
    float i = t - 12582912.0f;
    float f = fmaf(x, 1.4426950408889634f, -i);
    float y = f * 0.6931471805599453f;
    float p = fmaf(y, 0.0083333338f, 0.041666668f);
    p = fmaf(y, p, 0.16666667f);
    p = fmaf(y, p, 0.5f);
    p = fmaf(y, p, 1.0f);
    p = fmaf(y, p, 1.0f);
    return p * __int_as_float(((int)i + 127) << 23);
}
__device__ __forceinline__ void split2h(float v, __half& h, __half& l) {
    h = __float2half(v);
    l = __float2half((v - __half2float(h)) * 256.0f);
}

// ---------------------------------------------------------------------------
// Implicit-im2col conv GEMM, fp16 hi/lo, single-sync 3-stage mainloop.
// BM=128, BN=128, BK=32, 8 warps 2x4 (warp 64x32), occ 2.
// Blocks: blk0 = Wh*xl (f16 acc), blk1 = Wl*xh (f16 acc), blk2 = Wh*xh (f32).
// ---------------------------------------------------------------------------
#define CSTAGE (2*128*STR)
#define GSMEM_C (3*CSTAGE)

template <int TAPS>
__global__ __launch_bounds__(256, 2) void gemm_conv(
    const __half* __restrict__ W, float* __restrict__ C,
    const float* __restrict__ bias, int ptype)
{
    extern __shared__ char sm_[];
    uint32_t smb = smem_u32(sm_);
    int tid = threadIdx.x, lane = tid & 31, wid = tid >> 5;
    int wm = wid & 1, wn = wid >> 1;
    int b = blockIdx.z;
    int m0 = blockIdx.y * 128, n0 = blockIdx.x * 128;
    const int Kp = TAPS * 768;
    const int nk = TAPS * 24;
    const int nkc = TAPS * 16;
    const __half* XH = g_xt_h + (size_t)b * 4356 * 256;
    const __half* XL = g_xt_l + (size_t)b * 4356 * 256;
    const __half* Wb = W + (size_t)m0 * Kp;

    auto load = [&](int kt) {
        int st = kt % 3;
        uint32_t as = smb + st * CSTAGE;
        uint32_t bs = smb + st * CSTAGE + 128 * STR;
        int blk = kt / (TAPS * 8);
        int rem = kt - blk * (TAPS * 8);
        int t = rem >> 3, c0 = (rem & 7) << 5;
        int dy = (TAPS == 9) ? t / 3 : 1;
        int dx = (TAPS == 9) ? t % 3 : 1;
        const __half* buf = (blk == 0) ? XL : XH;   // blk0 pairs Wh with xl
#pragma unroll
        for (int u = 0; u < 2; u++) {
            int e = tid + u * 256;
            int row = e >> 2, ch = e & 3;
            cpa16(as + row * STR + ch * 16, Wb + (size_t)row * Kp + kt * 32 + ch * 8);
        }
#pragma unroll
        for (int u = 0; u < 2; u++) {
            int e = tid + u * 256;
            int row = e >> 2, ch = e & 3;
            int p = n0 + row, y = p >> 6, xx = p & 63;
            cpa16(bs + row * STR + ch * 16,
                  buf + (size_t)((y + dy) * 66 + (xx + dx)) * 256 + c0 + ch * 8);
        }
        asm volatile("cp.async.commit_group;" ::: "memory");
    };

    uint32_t acch[4][4][2];
#pragma unroll
    for (int i = 0; i < 4; i++)
#pragma unroll
        for (int j = 0; j < 4; j++) { acch[i][j][0] = 0u; acch[i][j][1] = 0u; }

    load(0);
    load(1);
    // phase 1: cross terms, f16 accumulator (single sync, early prefetch)
    for (int kt = 0; kt < nkc; kt++) {
        asm volatile("cp.async.wait_group 1;" ::: "memory");
        __syncthreads();
        if (kt + 2 < nk) load(kt + 2);
        else asm volatile("cp.async.commit_group;" ::: "memory");
        int st = kt % 3;
        uint32_t as = smb + st * CSTAGE + (wm * 64 + (lane & 15)) * STR + (lane >> 4) * 16;
        uint32_t bs = smb + st * CSTAGE + 128 * STR + (wn * 32 + (lane & 15)) * STR + (lane >> 4) * 16;
#pragma unroll
        for (int kk = 0; kk < 2; kk++) {
            uint32_t a[4][4], bb[2][4];
#pragma unroll
            for (int mt = 0; mt < 4; mt++) ldm4(a[mt], as + mt * 16 * STR + kk * 32);
#pragma unroll
            for (int nt = 0; nt < 2; nt++) ldm4(bb[nt], bs + nt * 16 * STR + kk * 32);
#pragma unroll
            for (int mt = 0; mt < 4; mt++)
#pragma unroll
                for (int n8 = 0; n8 < 4; n8++)
                    mma16hh(acch[mt][n8], a[mt], bb[n8 >> 1][n8 & 1], bb[n8 >> 1][(n8 & 1) + 2]);
        }
    }
    // fold cross terms (scaled 1/256) into f32 accumulator
    float accf[4][4][4];
#pragma unroll
    for (int mt = 0; mt < 4; mt++)
#pragma unroll
        for (int n8 = 0; n8 < 4; n8++) {
            float2 c0 = __half22float2(*(__half2*)&acch[mt][n8][0]);
            float2 c1 = __half22float2(*(__half2*)&acch[mt][n8][1]);
            accf[mt][n8][0] = c0.x * ISC;
            accf[mt][n8][1] = c0.y * ISC;
            accf[mt][n8][2] = c1.x * ISC;
            accf[mt][n8][3] = c1.y * ISC;
        }
    // phase 2: main term, f32 accumulator
    for (int kt = nkc; kt < nk; kt++) {
        asm volatile("cp.async.wait_group 1;" ::: "memory");
        __syncthreads();
        if (kt + 2 < nk) load(kt + 2);
        else asm volatile("cp.async.commit_group;" ::: "memory");
        int st = kt % 3;
        uint32_t as = smb + st * CSTAGE + (wm * 64 + (lane & 15)) * STR + (lane >> 4) * 16;
        uint32_t bs = smb + st * CSTAGE + 128 * STR + (wn * 32 + (lane & 15)) * STR + (lane >> 4) * 16;
#pragma unroll
        for (int kk = 0; kk < 2; kk++) {
            uint32_t a[4][4], bb[2][4];
#pragma unroll
            for (int mt = 0; mt < 4; mt++) ldm4(a[mt], as + mt * 16 * STR + kk * 32);
#pragma unroll
            for (int nt = 0; nt < 2; nt++) ldm4(bb[nt], bs + nt * 16 * STR + kk * 32);
#pragma unroll
            for (int mt = 0; mt < 4; mt++)
#pragma unroll
                for (int n8 = 0; n8 < 4; n8++)
                    mma16h(accf[mt][n8], a[mt], bb[n8 >> 1][n8 & 1], bb[n8 >> 1][(n8 & 1) + 2]);
        }
    }

    float* Cb = C + (size_t)b * NC * NPIX;
    float s1a[8], s2a[8];
#pragma unroll
    for (int i = 0; i < 8; i++) { s1a[i] = 0.f; s2a[i] = 0.f; }
#pragma unroll
    for (int mt = 0; mt < 4; mt++) {
        int row = m0 + wm * 64 + mt * 16 + (lane >> 2);
        float bi0 = bias[row], bi1 = bias[row + 8];
#pragma unroll
        for (int n8 = 0; n8 < 4; n8++) {
            int col = n0 + wn * 32 + n8 * 8 + (lane & 3) * 2;
            float2 v0, v1;
            v0.x = accf[mt][n8][0] + bi0; v0.y = accf[mt][n8][1] + bi0;
            v1.x = accf[mt][n8][2] + bi1; v1.y = accf[mt][n8][3] + bi1;
            *(float2*)&Cb[(size_t)row * 4096 + col] = v0;
            *(float2*)&Cb[(size_t)(row + 8) * 4096 + col] = v1;
            s1a[mt * 2 + 0] += v0.x + v0.y;
            s2a[mt * 2 + 0] += v0.x * v0.x + v0.y * v0.y;
            s1a[mt * 2 + 1] += v1.x + v1.y;
            s2a[mt * 2 + 1] += v1.x * v1.x + v1.y * v1.y;
        }
    }
#pragma unroll
    for (int i = 0; i < 8; i++) {
        s1a[i] += __shfl_xor_sync(0xFFFFFFFF, s1a[i], 1);
        s1a[i] += __shfl_xor_sync(0xFFFFFFFF, s1a[i], 2);
        s2a[i] += __shfl_xor_sync(0xFFFFFFFF, s2a[i], 1);
        s2a[i] += __shfl_xor_sync(0xFFFFFFFF, s2a[i], 2);
    }
    __syncthreads();
    float* smr = (float*)sm_;
    if ((lane & 3) == 0) {
#pragma unroll
        for (int mt = 0; mt < 4; mt++)
#pragma unroll
            for (int h = 0; h < 2; h++) {
                int r = wm * 64 + mt * 16 + h * 8 + (lane >> 2);
                smr[r * 4 + wn] = s1a[mt * 2 + h];
                smr[512 + r * 4 + wn] = s2a[mt * 2 + h];
            }
    }
    __syncthreads();
    if (tid < 128) {
        float a1 = smr[tid * 4] + smr[tid * 4 + 1] + smr[tid * 4 + 2] + smr[tid * 4 + 3];
        float a2 = smr[512 + tid * 4] + smr[512 + tid * 4 + 1]
                 + smr[512 + tid * 4 + 2] + smr[512 + tid * 4 + 3];
        int slot = b * 32 + blockIdx.x;
        g_psum1[(ptype * 128 + slot) * 256 + m0 + tid] = a1;
        g_psum2[(ptype * 128 + slot) * 256 + m0 + tid] = a2;
    }
}

// ---------------------------------------------------------------------------
// S GEMM fp16 hi/lo, single-sync 3-stage. BM=BN=128, occ 2.
// kt 0..15 cross (f16 acc), kt 16..23 main (f32 acc).
// ---------------------------------------------------------------------------
#define SSTAGE (128*STR)
#define GSMEM_S (6*SSTAGE)

__global__ __launch_bounds__(256, 2) void gemm_s(
    const __half* __restrict__ A, const __half* __restrict__ B)
{
    extern __shared__ char sm_[];
    uint32_t smb = smem_u32(sm_);
    int tid = threadIdx.x, lane = tid & 31, wid = tid >> 5;
    int wm = wid & 1, wn = wid >> 1;
    int bz = blockIdx.z;
    int m0 = blockIdx.y * 128, n0 = blockIdx.x * 128;
    const __half* Ab = A + (size_t)bz * 4096 * 768 + (size_t)m0 * 768;
    const __half* Bb = B + (size_t)bz * 4096 * 768 + (size_t)n0 * 768;
    const int nk = 24, nkc = 16;

    auto load = [&](int kt) {
        int st = kt % 3;
        uint32_t as = smb + st * SSTAGE;
        uint32_t bs = smb + 3 * SSTAGE + st * SSTAGE;
        int k0 = kt * 32;
#pragma unroll
        for (int i = 0; i < 2; i++) {
            int e = tid + i * 256;
            int row = e >> 2, ch = e & 3;
            cpa16(as + row * STR + ch * 16, Ab + (size_t)row * 768 + k0 + ch * 8);
            cpa16(bs + row * STR + ch * 16, Bb + (size_t)row * 768 + k0 + ch * 8);
        }
        asm volatile("cp.async.commit_group;" ::: "memory");
    };

    uint32_t acch[4][4][2];
#pragma unroll
    for (int i = 0; i < 4; i++)
#pragma unroll
        for (int j = 0; j < 4; j++) { acch[i][j][0] = 0u; acch[i][j][1] = 0u; }

    load(0);
    load(1);
    for (int kt = 0; kt < nkc; kt++) {
        asm volatile("cp.async.wait_group 1;" ::: "memory");
        __syncthreads();
        if (kt + 2 < nk) load(kt + 2);
        else asm volatile("cp.async.commit_group;" ::: "memory");
        int st = kt % 3;
        uint32_t as = smb + st * SSTAGE + (wm * 64 + (lane & 15)) * STR + (lane >> 4) * 16;
        uint32_t bs = smb + 3 * SSTAGE + st * SSTAGE + (wn * 32 + (lane & 15)) * STR + (lane >> 4) * 16;
#pragma unroll
        for (int kk = 0; kk < 2; kk++) {
            uint32_t a[4][4], bb[2][4];
#pragma unroll
            for (int mt = 0; mt < 4; mt++) ldm4(a[mt], as + mt * 16 * STR + kk * 32);
#pragma unroll
            for (int nt = 0; nt < 2; nt++) ldm4(bb[nt], bs + nt * 16 * STR + kk * 32);
#pragma unroll
            for (int mt = 0; mt < 4; mt++)
#pragma unroll
                for (int n8 = 0; n8 < 4; n8++)
                    mma16hh(acch[mt][n8], a[mt], bb[n8 >> 1][n8 & 1], bb[n8 >> 1][(n8 & 1) + 2]);
        }
    }
    float accf[4][4][4];
#pragma unroll
    for (int mt = 0; mt < 4; mt++)
#pragma unroll
        for (int n8 = 0; n8 < 4; n8++) {
            float2 c0 = __half22float2(*(__half2*)&acch[mt][n8][0]);
            float2 c1 = __half22float2(*(__half2*)&acch[mt][n8][1]);
            accf[mt][n8][0] = c0.x * ISC;
            accf[mt][n8][1] = c0.y * ISC;
            accf[mt][n8][2] = c1.x * ISC;
            accf[mt][n8][3] = c1.y * ISC;
        }
    for (int kt = nkc; kt < nk; kt++) {
        asm volatile("cp.async.wait_group 1;" ::: "memory");
        __syncthreads();
        if (kt + 2 < nk) load(kt + 2);
        else asm volatile("cp.async.commit_group;" ::: "memory");
        int st = kt % 3;
        uint32_t as = smb + st * SSTAGE + (wm * 64 + (lane & 15)) * STR + (lane >> 4) * 16;
        uint32_t bs = smb + 3 * SSTAGE + st * SSTAGE + (wn * 32 + (lane & 15)) * STR + (lane >> 4) * 16;
#pragma unroll
        for (int kk = 0; kk < 2; kk++) {
            uint32_t a[4][4], bb[2][4];
#pragma unroll
            for (int mt = 0; mt < 4; mt++) ldm4(a[mt], as + mt * 16 * STR + kk * 32);
#pragma unroll
            for (int nt = 0; nt < 2; nt++) ldm4(bb[nt], bs + nt * 16 * STR + kk * 32);
#pragma unroll
            for (int mt = 0; mt < 4; mt++)
#pragma unroll
                for (int n8 = 0; n8 < 4; n8++)
                    mma16h(accf[mt][n8], a[mt], bb[n8 >> 1][n8 & 1], bb[n8 >> 1][(n8 & 1) + 2]);
        }
    }

    // epilogue: per-warp 32-k group max -> exp -> fp16 P, partial (m, sum)
    __half* Pb = g_P16 + (size_t)bz * 4096 * 4096;
    int g = blockIdx.x * 4 + wn;
#pragma unroll
    for (int mt = 0; mt < 4; mt++) {
#pragma unroll
        for (int h = 0; h < 2; h++) {
            float m = -3.4e38f;
#pragma unroll
            for (int n8 = 0; n8 < 4; n8++)
                m = fmaxf(m, fmaxf(accf[mt][n8][2 * h], accf[mt][n8][2 * h + 1]));
            m = fmaxf(m, __shfl_xor_sync(0xFFFFFFFF, m, 1));
            m = fmaxf(m, __shfl_xor_sync(0xFFFFFFFF, m, 2));
            int row = m0 + wm * 64 + mt * 16 + h * 8 + (lane >> 2);
            float s = 0.f;
#pragma unroll
            for (int n8 = 0; n8 < 4; n8++) {
                float e0 = fexp(accf[mt][n8][2 * h] - m);
                float e1 = fexp(accf[mt][n8][2 * h + 1] - m);
                s += e0 + e1;
                int col = n0 + wn * 32 + n8 * 8 + (lane & 3) * 2;
                *(__half2*)&Pb[(size_t)row * 4096 + col] = __floats2half2_rn(e0, e1);
            }
            s += __shfl_xor_sync(0xFFFFFFFF, s, 1);
            s += __shfl_xor_sync(0xFFFFFFFF, s, 2);
            if ((lane & 3) == 0) {
                size_t o = ((size_t)bz * 128 + g) * 4096 + row;
                g_pm[o] = m;
                g_ps[o] = s;
            }
        }
    }
}

// combine 128 group partials + border key (8 sbp partials) -> m, 1/Z, bw
__global__ void sm_combine() {
    int i = blockIdx.x * 256 + threadIdx.x;
    int b = i >> 12, q = i & 4095;
    float sbv = 0.f;
#pragma unroll
    for (int j = 0; j < 8; j++) sbv += g_sbp[j * (NB * NPIX) + i];
    float mg = sbv;
#pragma unroll 8
    for (int t = 0; t < 128; t++)
        mg = fmaxf(mg, g_pm[((size_t)b * 128 + t) * 4096 + q]);
    float Z = 260.f * fexp(sbv - mg);
    float eb = Z;
#pragma unroll 8
    for (int t = 0; t < 128; t++) {
        size_t o = ((size_t)b * 128 + t) * 4096 + q;
        Z += fexp(g_pm[o] - mg) * g_ps[o];
    }
    float iz = 1.f / Z;
    g_m[i] = mg;
    g_iz[i] = iz;
    g_bw[i] = eb * iz;
}

// ---------------------------------------------------------------------------
// Fused O GEMM (fp16 data, f32 acc) — R12 form (two-sync, in-iter B fill).
// BM=256, BN=64, BK=32, occ 2.
// ---------------------------------------------------------------------------
#define OASTG (256*STR)
#define OB0   (3*OASTG)
#define OBSTG (64*STR)
#define GSMEM_O (OB0 + 2*OBSTG)

__global__ __launch_bounds__(256, 2) void gemm_o(float* __restrict__ Cout)
{
    extern __shared__ char sm_[];
    uint32_t smb = smem_u32(sm_);
    int tid = threadIdx.x, lane = tid & 31, wid = tid >> 5;
    int wm = wid >> 1, wn = wid & 1;
    int b = blockIdx.z;
    int n0 = blockIdx.x * 64;
    const __half* Vb = g_vf + (size_t)b * NC * NPIX;
    const int nk = 128;

    int fq = tid >> 2, fqt = tid & 3;
    int q = n0 + fq;
    float mq = g_m[b * 4096 + q];
    float izq = g_iz[b * 4096 + q];
    const __half* Pq = g_P16 + ((size_t)b * 4096 + q) * 4096 + fqt * 8;
    const float* pmq = g_pm + (size_t)b * 128 * 4096 + q;

    auto loadA = [&](int kt) {
        int st = kt % 3;
#pragma unroll
        for (int u = 0; u < 4; u++) {
            int e = tid + u * 256;
            int row = e >> 2, ch = e & 3;
            cpa16(smb + st * OASTG + row * STR + ch * 16,
                  Vb + (size_t)row * 4096 + kt * 32 + ch * 8);
        }
        asm volatile("cp.async.commit_group;" ::: "memory");
    };

    float acc[4][4][4];
#pragma unroll
    for (int i = 0; i < 4; i++)
#pragma unroll
        for (int j = 0; j < 4; j++)
#pragma unroll
            for (int r = 0; r < 4; r++) acc[i][j][r] = 0.f;

    uint4 pf;
    float pmv;
    loadA(0);
    loadA(1);
    pf = *(const uint4*)Pq;
    pmv = pmq[0];

    for (int kt = 0; kt < nk; kt++) {
        asm volatile("cp.async.wait_group 1;" ::: "memory");
        __syncthreads();
        {
            float sc = fexp(pmv - mq) * izq;
            __half2 s2 = __float2half2_rn(sc);
            __half2* ph = (__half2*)&pf;
            uint4 o;
            __half2* oh = (__half2*)&o;
            oh[0] = __hmul2(ph[0], s2);
            oh[1] = __hmul2(ph[1], s2);
            oh[2] = __hmul2(ph[2], s2);
            oh[3] = __hmul2(ph[3], s2);
            *(uint4*)(sm_ + OB0 + (kt & 1) * OBSTG + fq * STR + fqt * 16) = o;
        }
        if (kt + 1 < nk) {
            pf = *(const uint4*)(Pq + (kt + 1) * 32);
            pmv = pmq[(size_t)(kt + 1) * 4096];
        }
        if (kt + 2 < nk) loadA(kt + 2);
        else asm volatile("cp.async.commit_group;" ::: "memory");
        __syncthreads();

        int st = kt % 3, b2 = kt & 1;
        uint32_t as_ = smb + st * OASTG + (wm * 64 + (lane & 15)) * STR + (lane >> 4) * 16;
        uint32_t bs_ = smb + OB0 + b2 * OBSTG + (wn * 32 + (lane & 15)) * STR + (lane >> 4) * 16;
#pragma unroll
        for (int kk = 0; kk < 2; kk++) {
            uint32_t a[4][4], bb[2][4];
#pragma unroll
            for (int mt = 0; mt < 4; mt++) ldm4(a[mt], as_ + mt * 16 * STR + kk * 32);
#pragma unroll
            for (int nt = 0; nt < 2; nt++) ldm4(bb[nt], bs_ + nt * 16 * STR + kk * 32);
#pragma unroll
            for (int mt = 0; mt < 4; mt++)
#pragma unroll
                for (int n8 = 0; n8 < 4; n8++)
                    mma16h(acc[mt][n8], a[mt], bb[n8 >> 1][n8 & 1], bb[n8 >> 1][(n8 & 1) + 2]);
        }
    }

    float* Cb = Cout + (size_t)b * NC * NPIX;
    const float* bwp = g_bw + (size_t)b * 4096;
#pragma unroll
    for (int mt = 0; mt < 4; mt++) {
        int row = wm * 64 + mt * 16 + (lane >> 2);
        float vb0 = g_vbv[row], vb1 = g_vbv[row + 8];
#pragma unroll
        for (int n8 = 0; n8 < 4; n8++) {
            int col = n0 + wn * 32 + n8 * 8 + (lane & 3) * 2;
            float w0 = bwp[col], w1 = bwp[col + 1];
            float2 v0, v1;
            v0.x = fmaf(w0, vb0, acc[mt][n8][0]); v0.y = fmaf(w1, vb0, acc[mt][n8][1]);
            v1.x = fmaf(w0, vb1, acc[mt][n8][2]); v1.y = fmaf(w1, vb1, acc[mt][n8][3]);
            *(float2*)&Cb[(size_t)row * 4096 + col] = v0;
            *(float2*)&Cb[(size_t)(row + 8) * 4096 + col] = v1;
        }
    }
}

// ---- prep kernels ----
// zero only the 260 border positions of each 66x66 grid (both buffers)
__global__ void zero_border() {
    int idx = blockIdx.x * 256 + threadIdx.x;    // NB*260*32 uint4 slots
    if (idx >= NB * 260 * 32) return;
    int u = idx & 31;
    int pi = (idx >> 5) % 260;
    int b = idx / (260 * 32);
    int y, x;
    if (pi < 66)       { y = 0;  x = pi; }
    else if (pi < 132) { y = 65; x = pi - 66; }
    else if (pi < 196) { y = pi - 132 + 1; x = 0; }
    else               { y = pi - 196 + 1; x = 65; }
    size_t o = ((size_t)b * 4356 + y * 66 + x) * 32 + u;
    ((uint4*)g_xt_h)[o] = make_uint4(0, 0, 0, 0);
    ((uint4*)g_xt_l)[o] = make_uint4(0, 0, 0, 0);
}

__global__ void xt_fill(const float* __restrict__ x) {
    __shared__ float tile[32][33];
    int b = blockIdx.z;
    int p0 = blockIdx.x * 32, c0 = blockIdx.y * 32;
    int tx = threadIdx.x, ty = threadIdx.y;
    const float* s = x + (size_t)b * NC * NPIX;
    for (int j = 0; j < 32; j += 8)
        tile[ty + j][tx] = s[(size_t)(c0 + ty + j) * NPIX + p0 + tx];
    __syncthreads();
    for (int j = 0; j < 32; j += 8) {
        int p = p0 + ty + j, y = p >> 6, xx = p & 63;
        size_t o = ((size_t)b * 4356 + (y + 1) * 66 + (xx + 1)) * 256 + c0 + tx;
        __half h, l;
        split2h(tile[tx][ty + j], h, l);
        g_xt_h[o] = h;
        g_xt_l[o] = l;
    }
}

// Wq blocks [h | l*256 | h], k ordering t*256+c within block
__global__ void wsplit_q(const float* __restrict__ w) {
    int idx = blockIdx.x * 256 + threadIdx.x;
    if (idx >= NC * 2304) return;
    int m = idx / 2304, r = idx % 2304;
    int c = r / 9, t = r % 9;
    __half h, l;
    split2h(w[idx], h, l);
    size_t base = (size_t)m * 6912 + t * 256 + c;
    g_wqh[base] = h;
    g_wqh[base + 2304] = l;
    g_wqh[base + 4608] = h;
}

__global__ void wsplit1(const float* __restrict__ w, __half* __restrict__ o) {
    int idx = blockIdx.x * 256 + threadIdx.x;
    if (idx >= NC * NC) return;
    int m = idx / NC, c = idx % NC;
    __half h, l;
    split2h(w[idx], h, l);
    size_t base = (size_t)m * 768 + c;
    o[base] = h;
    o[base + 256] = l;
    o[base + 512] = h;
}

// transpose [c][pix] -> [pix][c3] with affine; patA(Q): [h,l,h]; else(K): [l,h,h]
// Q path also emits border-score partials
__global__ void tsplit(const float* __restrict__ src, __half* __restrict__ dst,
                       const float* __restrict__ aa, const float* __restrict__ ad,
                       int patA, const float* __restrict__ kbv, float* __restrict__ sbp) {
    __shared__ float tile[32][33];
    __shared__ float sbred[8][32];
    int b = blockIdx.z;
    int p0 = blockIdx.x * 32, c0 = blockIdx.y * 32;
    int tx = threadIdx.x, ty = threadIdx.y;
    const float* s = src + (size_t)b * NC * NPIX;
    for (int j = 0; j < 32; j += 8) {
        float a = aa[c0 + ty + j], d = ad[c0 + ty + j];
        tile[ty + j][tx] = fmaf(a, s[(size_t)(c0 + ty + j) * NPIX + p0 + tx], d);
    }
    __syncthreads();
    for (int j = 0; j < 32; j += 8) {
        __half h, l;
        split2h(tile[tx][ty + j], h, l);
        __half* o = dst + ((size_t)b * 4096 + p0 + ty + j) * 768 + c0 + tx;
        o[0] = patA ? h : l;
        o[256] = patA ? l : h;
        o[512] = h;
    }
    if (kbv) {
        float part = 0.f;
#pragma unroll
        for (int c = ty; c < 32; c += 8)
            part = fmaf(kbv[c0 + c], tile[c][tx], part);
        sbred[ty][tx] = part;
        __syncthreads();
        if (ty == 0) {
            float sum = 0.f;
#pragma unroll
            for (int j = 0; j < 8; j++) sum += sbred[j][tx];
            sbp[(size_t)blockIdx.y * (NB * NPIX) + b * NPIX + p0 + tx] = sum;
        }
    }
}

__global__ void vf_k() {
    size_t i4 = (size_t)blockIdx.x * 256 + threadIdx.x;
    size_t e = i4 * 4;
    int c = (int)((e >> 12) & 255);
    float a = g_a[512 + c], d = g_dd[512 + c];
    float4 v = *(float4*)(g_vc + e);
    __half h[4];
    h[0] = __float2half(fmaf(a, v.x, d));
    h[1] = __float2half(fmaf(a, v.y, d));
    h[2] = __float2half(fmaf(a, v.z, d));
    h[3] = __float2half(fmaf(a, v.w, d));
    *(uint2*)(g_vf + e) = *(uint2*)h;
}

// tiny stats: sum 128 conv partials per channel
__global__ void stats_k(const float* __restrict__ bq, const float* __restrict__ gq, const float* __restrict__ betaq,
                        const float* __restrict__ bk, const float* __restrict__ gk, const float* __restrict__ betak,
                        const float* __restrict__ bv, const float* __restrict__ gv, const float* __restrict__ betav)
{
    int t = blockIdx.x;
    int c = threadIdx.x;
    float S1f = 0.f, S2f = 0.f;
    for (int j = 0; j < 128; j++) {
        S1f += g_psum1[(t * 128 + j) * 256 + c];
        S2f += g_psum2[(t * 128 + j) * 256 + c];
    }
    double S1 = S1f, S2 = S2f, cnt = 16384.0;
    float bias = (t == 0) ? bq[c] : (t == 1) ? bk[c] : bv[c];
    float g    = (t == 0) ? gq[c] : (t == 1) ? gk[c] : gv[c];
    float be   = (t == 0) ? betaq[c] : (t == 1) ? betak[c] : betav[c];
    if (t > 0) {
        cnt = 17424.0;
        S1 += 1040.0 * (double)bias;
        S2 += 1040.0 * (double)bias * (double)bias;
    }
    double mean = S1 / cnt;
    double var = S2 / cnt - mean * mean;
    float a = g * rsqrtf((float)var + 1e-5f);
    float d = be - a * (float)mean;
    g_a[t * NC + c] = a;
    g_dd[t * NC + c] = d;
    if (t == 1) g_kbv[c] = fmaf(a, bias, d);
    if (t == 2) g_vbv[c] = fmaf(a, bias, d);
}

// ---------------------------------------------------------------------------
extern "C" void kernel_launch(void* const* d_in, const int* in_sizes, int n_in,
                              void* d_out, int out_size)
{
    const float* x     = (const float*)d_in[0];
    const float* Wq    = (const float*)d_in[1];
    const float* bq    = (const float*)d_in[2];
    const float* gq    = (const float*)d_in[3];
    const float* betaq = (const float*)d_in[4];
    const float* Wk    = (const float*)d_in[5];
    const float* bk    = (const float*)d_in[6];
    const float* gk    = (const float*)d_in[7];
    const float* betak = (const float*)d_in[8];
    const float* Wv    = (const float*)d_in[9];
    const float* bv    = (const float*)d_in[10];
    const float* gv    = (const float*)d_in[11];
    const float* betav = (const float*)d_in[12];
    float* out = (float*)d_out;

    cudaFuncSetAttribute(gemm_conv<9>, cudaFuncAttributeMaxDynamicSharedMemorySize, GSMEM_C);
    cudaFuncSetAttribute(gemm_conv<1>, cudaFuncAttributeMaxDynamicSharedMemorySize, GSMEM_C);
    cudaFuncSetAttribute(gemm_s, cudaFuncAttributeMaxDynamicSharedMemorySize, GSMEM_S);
    cudaFuncSetAttribute(gemm_o, cudaFuncAttributeMaxDynamicSharedMemorySize, GSMEM_O);

    __half *p_wqh, *p_wkh, *p_wvh, *p_qth, *p_kth;
    float *p_qc, *p_kc, *p_vc, *p_a, *p_dd, *p_kbv, *p_sbp;
    cudaGetSymbolAddress((void**)&p_wqh, g_wqh);
    cudaGetSymbolAddress((void**)&p_wkh, g_wkh);
    cudaGetSymbolAddress((void**)&p_wvh, g_wvh);
    cudaGetSymbolAddress((void**)&p_qth, g_qth);
    cudaGetSymbolAddress((void**)&p_kth, g_kth);
    cudaGetSymbolAddress((void**)&p_qc,  g_qc);
    cudaGetSymbolAddress((void**)&p_kc,  g_kc);
    cudaGetSymbolAddress((void**)&p_vc,  g_vc);
    cudaGetSymbolAddress((void**)&p_a,   g_a);
    cudaGetSymbolAddress((void**)&p_dd,  g_dd);
    cudaGetSymbolAddress((void**)&p_kbv, g_kbv);
    cudaGetSymbolAddress((void**)&p_sbp, g_sbp);

    // 1. border zero + padded transposed hi/lo x (fp16) + weight splits
    zero_border<<<(NB * 260 * 32 + 255) / 256, 256>>>();
    xt_fill<<<dim3(128, 8, NB), dim3(32, 8)>>>(x);
    wsplit_q<<<(NC * 2304 + 255) / 256, 256>>>(Wq);
    wsplit1<<<(NC * NC + 255) / 256, 256>>>(Wk, p_wkh);
    wsplit1<<<(NC * NC + 255) / 256, 256>>>(Wv, p_wvh);

    // 2. convs (implicit im2col, fp16 hi/lo, mixed-acc, single-sync)
    gemm_conv<9><<<dim3(32, 2, NB), 256, GSMEM_C>>>(p_wqh, p_qc, bq, 0);
    gemm_conv<1><<<dim3(32, 2, NB), 256, GSMEM_C>>>(p_wkh, p_kc, bk, 1);
    gemm_conv<1><<<dim3(32, 2, NB), 256, GSMEM_C>>>(p_wvh, p_vc, bv, 2);

    // 3. BN stats (tiny) + splits (Q path emits border partials) + V fp16
    stats_k<<<3, 256>>>(bq, gq, betaq, bk, gk, betak, bv, gv, betav);
    tsplit<<<dim3(128, 8, NB), dim3(32, 8)>>>(p_qc, p_qth, p_a, p_dd, 1, p_kbv, p_sbp);
    tsplit<<<dim3(128, 8, NB), dim3(32, 8)>>>(p_kc, p_kth, p_a + 256, p_dd + 256, 0, 0, 0);
    vf_k<<<(int)(((size_t)NB * NC * NPIX / 4) / 256), 256>>>();

    // 4. S GEMM (fp16 hi/lo, mixed-acc, single-sync) -> fp16 exp-tiles + partials
    gemm_s<<<dim3(32, 32, NB), 256, GSMEM_S>>>(p_qth, p_kth);

    // 5. combine partials -> m, 1/Z, bw
    sm_combine<<<64, 256>>>();

    // 6. fused O GEMM (fp16, f32 acc, occ 2)
    gemm_o<<<dim3(64, 1, NB), 256, GSMEM_O>>>(out);
}

// round 16
// speedup vs baseline: 1.5367x; 1.0024x over previous
#include <cuda_runtime.h>
#include <cuda_fp16.h>
#include <math.h>
#include <stdint.h>

#define NB 4
#define NC 256
#define NPIX 4096
#define STR 80
#define ISC (1.0f/256.0f)

// ---- static device scratch ----
__device__ __half g_xt_h[(size_t)NB*4356*256];   // padded x fp16 hi, [b][pix66][c]
__device__ __half g_xt_l[(size_t)NB*4356*256];   // (x-hi)*256
__device__ __half g_wqh[NC*6912];                // Wq blocks [h | l*256 | h], k=t*256+c
__device__ __half g_wkh[NC*768];
__device__ __half g_wvh[NC*768];
__device__ float g_qc[(size_t)NB*NC*NPIX];
__device__ float g_kc[(size_t)NB*NC*NPIX];
__device__ float g_vc[(size_t)NB*NC*NPIX];
__device__ __half g_qth[(size_t)NB*NPIX*768];    // BN(Q)^T blocks [h | l | h]
__device__ __half g_kth[(size_t)NB*NPIX*768];    // BN(K)^T blocks [l | h | h]
__device__ __half g_vf[(size_t)NB*NC*NPIX];      // BN(V) fp16 [b][c][k]
__device__ __half g_P16[(size_t)NB*NPIX*NPIX];   // exp(s-lm) fp16 [b][q][k]
__device__ float g_pm[(size_t)NB*128*NPIX];      // per-32k-group max
__device__ float g_ps[(size_t)NB*128*NPIX];      // per-32k-group sum
__device__ float g_psum1[3*128*256];             // conv partial sums [t][slot][ch]
__device__ float g_psum2[3*128*256];
__device__ float g_sbp[8*NB*NPIX];               // border-score partials [cblk][b*q]
__device__ float g_bw[NB*NPIX];
__device__ float g_m[NB*NPIX];
__device__ float g_iz[NB*NPIX];
__device__ float g_a[3*NC];
__device__ float g_dd[3*NC];
__device__ float g_kbv[NC];
__device__ float g_vbv[NC];

// ---- helpers ----
__device__ __forceinline__ uint32_t smem_u32(const void* p) {
    uint32_t a;
    asm("{ .reg .u64 t; cvta.to.shared.u64 t, %1; cvt.u32.u64 %0, t; }" : "=r"(a) : "l"(p));
    return a;
}
__device__ __forceinline__ void cpa16(uint32_t s, const void* g) {
    asm volatile("cp.async.cg.shared.global [%0], [%1], 16;" :: "r"(s), "l"(g));
}
__device__ __forceinline__ void ldm4(uint32_t* r, uint32_t addr) {
    asm volatile("ldmatrix.sync.aligned.m8n8.x4.shared.b16 {%0,%1,%2,%3}, [%4];"
                 : "=r"(r[0]), "=r"(r[1]), "=r"(r[2]), "=r"(r[3]) : "r"(addr));
}
// fp16 data, f32 accum
__device__ __forceinline__ void mma16h(float* d, const uint32_t* a, uint32_t b0, uint32_t b1) {
    asm volatile(
        "mma.sync.aligned.m16n8k16.row.col.f32.f16.f16.f32 "
        "{%0,%1,%2,%3}, {%4,%5,%6,%7}, {%8,%9}, {%0,%1,%2,%3};"
        : "+f"(d[0]), "+f"(d[1]), "+f"(d[2]), "+f"(d[3])
        : "r"(a[0]), "r"(a[1]), "r"(a[2]), "r"(a[3]), "r"(b0), "r"(b1));
}
// fp16 data, f16 accum
__device__ __forceinline__ void mma16hh(uint32_t* d, const uint32_t* a, uint32_t b0, uint32_t b1) {
    asm volatile(
        "mma.sync.aligned.m16n8k16.row.col.f16.f16.f16.f16 "
        "{%0,%1}, {%2,%3,%4,%5}, {%6,%7}, {%0,%1};"
        : "+r"(d[0]), "+r"(d[1])
        : "r"(a[0]), "r"(a[1]), "r"(a[2]), "r"(a[3]), "r"(b0), "r"(b1));
}
__device__ __forceinline__ float fexp(float x) {
    x = fmaxf(x, -87.0f);
    float t = fmaf(x, 1.4426950408889634f, 12582912.0f);
    float i = t - 12582912.0f;
    float f = fmaf(x, 1.4426950408889634f, -i);
    float y = f * 0.6931471805599453f;
    float p = fmaf(y, 0.0083333338f, 0.041666668f);
    p = fmaf(y, p, 0.16666667f);
    p = fmaf(y, p, 0.5f);
    p = fmaf(y, p, 1.0f);
    p = fmaf(y, p, 1.0f);
    return p * __int_as_float(((int)i + 127) << 23);
}
__device__ __forceinline__ void split2h(float v, __half& h, __half& l) {
    h = __float2half(v);
    l = __float2half((v - __half2float(h)) * 256.0f);
}

// ---------------------------------------------------------------------------
// Implicit-im2col conv GEMM, fp16 hi/lo, single-sync 3-stage mainloop.
// BM=128, BN=128, BK=32, 8 warps 2x4 (warp 64x32), occ 2.
// Blocks: blk0 = Wh*xl (f16 acc), blk1 = Wl*xh (f16 acc), blk2 = Wh*xh (f32).
// ---------------------------------------------------------------------------
#define CSTAGE (2*128*STR)
#define GSMEM_C (3*CSTAGE)

template <int TAPS>
__global__ __launch_bounds__(256, 2) void gemm_conv(
    const __half* __restrict__ W, float* __restrict__ C,
    const float* __restrict__ bias, int ptype)
{
    extern __shared__ char sm_[];
    uint32_t smb = smem_u32(sm_);
    int tid = threadIdx.x, lane = tid & 31, wid = tid >> 5;
    int wm = wid & 1, wn = wid >> 1;
    int b = blockIdx.z;
    int m0 = blockIdx.y * 128, n0 = blockIdx.x * 128;
    const int Kp = TAPS * 768;
    const int nk = TAPS * 24;
    const int nkc = TAPS * 16;
    const __half* XH = g_xt_h + (size_t)b * 4356 * 256;
    const __half* XL = g_xt_l + (size_t)b * 4356 * 256;
    const __half* Wb = W + (size_t)m0 * Kp;

    auto load = [&](int kt) {
        int st = kt % 3;
        uint32_t as = smb + st * CSTAGE;
        uint32_t bs = smb + st * CSTAGE + 128 * STR;
        int blk = kt / (TAPS * 8);
        int rem = kt - blk * (TAPS * 8);
        int t = rem >> 3, c0 = (rem & 7) << 5;
        int dy = (TAPS == 9) ? t / 3 : 1;
        int dx = (TAPS == 9) ? t % 3 : 1;
        const __half* buf = (blk == 0) ? XL : XH;   // blk0 pairs Wh with xl
#pragma unroll
        for (int u = 0; u < 2; u++) {
            int e = tid + u * 256;
            int row = e >> 2, ch = e & 3;
            cpa16(as + row * STR + ch * 16, Wb + (size_t)row * Kp + kt * 32 + ch * 8);
        }
#pragma unroll
        for (int u = 0; u < 2; u++) {
            int e = tid + u * 256;
            int row = e >> 2, ch = e & 3;
            int p = n0 + row, y = p >> 6, xx = p & 63;
            cpa16(bs + row * STR + ch * 16,
                  buf + (size_t)((y + dy) * 66 + (xx + dx)) * 256 + c0 + ch * 8);
        }
        asm volatile("cp.async.commit_group;" ::: "memory");
    };

    uint32_t acch[4][4][2];
#pragma unroll
    for (int i = 0; i < 4; i++)
#pragma unroll
        for (int j = 0; j < 4; j++) { acch[i][j][0] = 0u; acch[i][j][1] = 0u; }

    load(0);
    load(1);
    // phase 1: cross terms, f16 accumulator (single sync, early prefetch)
    for (int kt = 0; kt < nkc; kt++) {
        asm volatile("cp.async.wait_group 1;" ::: "memory");
        __syncthreads();
        if (kt + 2 < nk) load(kt + 2);
        else asm volatile("cp.async.commit_group;" ::: "memory");
        int st = kt % 3;
        uint32_t as = smb + st * CSTAGE + (wm * 64 + (lane & 15)) * STR + (lane >> 4) * 16;
        uint32_t bs = smb + st * CSTAGE + 128 * STR + (wn * 32 + (lane & 15)) * STR + (lane >> 4) * 16;
#pragma unroll
        for (int kk = 0; kk < 2; kk++) {
            uint32_t a[4][4], bb[2][4];
#pragma unroll
            for (int mt = 0; mt < 4; mt++) ldm4(a[mt], as + mt * 16 * STR + kk * 32);
#pragma unroll
            for (int nt = 0; nt < 2; nt++) ldm4(bb[nt], bs + nt * 16 * STR + kk * 32);
#pragma unroll
            for (int mt = 0; mt < 4; mt++)
#pragma unroll
                for (int n8 = 0; n8 < 4; n8++)
                    mma16hh(acch[mt][n8], a[mt], bb[n8 >> 1][n8 & 1], bb[n8 >> 1][(n8 & 1) + 2]);
        }
    }
    // fold cross terms (scaled 1/256) into f32 accumulator
    float accf[4][4][4];
#pragma unroll
    for (int mt = 0; mt < 4; mt++)
#pragma unroll
        for (int n8 = 0; n8 < 4; n8++) {
            float2 c0 = __half22float2(*(__half2*)&acch[mt][n8][0]);
            float2 c1 = __half22float2(*(__half2*)&acch[mt][n8][1]);
            accf[mt][n8][0] = c0.x * ISC;
            accf[mt][n8][1] = c0.y * ISC;
            accf[mt][n8][2] = c1.x * ISC;
            accf[mt][n8][3] = c1.y * ISC;
        }
    // phase 2: main term, f32 accumulator
    for (int kt = nkc; kt < nk; kt++) {
        asm volatile("cp.async.wait_group 1;" ::: "memory");
        __syncthreads();
        if (kt + 2 < nk) load(kt + 2);
        else asm volatile("cp.async.commit_group;" ::: "memory");
        int st = kt % 3;
        uint32_t as = smb + st * CSTAGE + (wm * 64 + (lane & 15)) * STR + (lane >> 4) * 16;
        uint32_t bs = smb + st * CSTAGE + 128 * STR + (wn * 32 + (lane & 15)) * STR + (lane >> 4) * 16;
#pragma unroll
        for (int kk = 0; kk < 2; kk++) {
            uint32_t a[4][4], bb[2][4];
#pragma unroll
            for (int mt = 0; mt < 4; mt++) ldm4(a[mt], as + mt * 16 * STR + kk * 32);
#pragma unroll
            for (int nt = 0; nt < 2; nt++) ldm4(bb[nt], bs + nt * 16 * STR + kk * 32);
#pragma unroll
            for (int mt = 0; mt < 4; mt++)
#pragma unroll
                for (int n8 = 0; n8 < 4; n8++)
                    mma16h(accf[mt][n8], a[mt], bb[n8 >> 1][n8 & 1], bb[n8 >> 1][(n8 & 1) + 2]);
        }
    }

    float* Cb = C + (size_t)b * NC * NPIX;
    float s1a[8], s2a[8];
#pragma unroll
    for (int i = 0; i < 8; i++) { s1a[i] = 0.f; s2a[i] = 0.f; }
#pragma unroll
    for (int mt = 0; mt < 4; mt++) {
        int row = m0 + wm * 64 + mt * 16 + (lane >> 2);
        float bi0 = bias[row], bi1 = bias[row + 8];
#pragma unroll
        for (int n8 = 0; n8 < 4; n8++) {
            int col = n0 + wn * 32 + n8 * 8 + (lane & 3) * 2;
            float2 v0, v1;
            v0.x = accf[mt][n8][0] + bi0; v0.y = accf[mt][n8][1] + bi0;
            v1.x = accf[mt][n8][2] + bi1; v1.y = accf[mt][n8][3] + bi1;
            *(float2*)&Cb[(size_t)row * 4096 + col] = v0;
            *(float2*)&Cb[(size_t)(row + 8) * 4096 + col] = v1;
            s1a[mt * 2 + 0] += v0.x + v0.y;
            s2a[mt * 2 + 0] += v0.x * v0.x + v0.y * v0.y;
            s1a[mt * 2 + 1] += v1.x + v1.y;
            s2a[mt * 2 + 1] += v1.x * v1.x + v1.y * v1.y;
        }
    }
#pragma unroll
    for (int i = 0; i < 8; i++) {
        s1a[i] += __shfl_xor_sync(0xFFFFFFFF, s1a[i], 1);
        s1a[i] += __shfl_xor_sync(0xFFFFFFFF, s1a[i], 2);
        s2a[i] += __shfl_xor_sync(0xFFFFFFFF, s2a[i], 1);
        s2a[i] += __shfl_xor_sync(0xFFFFFFFF, s2a[i], 2);
    }
    __syncthreads();
    float* smr = (float*)sm_;
    if ((lane & 3) == 0) {
#pragma unroll
        for (int mt = 0; mt < 4; mt++)
#pragma unroll
            for (int h = 0; h < 2; h++) {
                int r = wm * 64 + mt * 16 + h * 8 + (lane >> 2);
                smr[r * 4 + wn] = s1a[mt * 2 + h];
                smr[512 + r * 4 + wn] = s2a[mt * 2 + h];
            }
    }
    __syncthreads();
    if (tid < 128) {
        float a1 = smr[tid * 4] + smr[tid * 4 + 1] + smr[tid * 4 + 2] + smr[tid * 4 + 3];
        float a2 = smr[512 + tid * 4] + smr[512 + tid * 4 + 1]
                 + smr[512 + tid * 4 + 2] + smr[512 + tid * 4 + 3];
        int slot = b * 32 + blockIdx.x;
        g_psum1[(ptype * 128 + slot) * 256 + m0 + tid] = a1;
        g_psum2[(ptype * 128 + slot) * 256 + m0 + tid] = a2;
    }
}

// ---------------------------------------------------------------------------
// S GEMM fp16 hi/lo, single-sync 3-stage. BM=BN=128, occ 2.
// kt 0..15 cross (f16 acc), kt 16..23 main (f32 acc).
// ---------------------------------------------------------------------------
#define SSTAGE (128*STR)
#define GSMEM_S (6*SSTAGE)

__global__ __launch_bounds__(256, 2) void gemm_s(
    const __half* __restrict__ A, const __half* __restrict__ B)
{
    extern __shared__ char sm_[];
    uint32_t smb = smem_u32(sm_);
    int tid = threadIdx.x, lane = tid & 31, wid = tid >> 5;
    int wm = wid & 1, wn = wid >> 1;
    int bz = blockIdx.z;
    int m0 = blockIdx.y * 128, n0 = blockIdx.x * 128;
    const __half* Ab = A + (size_t)bz * 4096 * 768 + (size_t)m0 * 768;
    const __half* Bb = B + (size_t)bz * 4096 * 768 + (size_t)n0 * 768;
    const int nk = 24, nkc = 16;

    auto load = [&](int kt) {
        int st = kt % 3;
        uint32_t as = smb + st * SSTAGE;
        uint32_t bs = smb + 3 * SSTAGE + st * SSTAGE;
        int k0 = kt * 32;
#pragma unroll
        for (int i = 0; i < 2; i++) {
            int e = tid + i * 256;
            int row = e >> 2, ch = e & 3;
            cpa16(as + row * STR + ch * 16, Ab + (size_t)row * 768 + k0 + ch * 8);
            cpa16(bs + row * STR + ch * 16, Bb + (size_t)row * 768 + k0 + ch * 8);
        }
        asm volatile("cp.async.commit_group;" ::: "memory");
    };

    uint32_t acch[4][4][2];
#pragma unroll
    for (int i = 0; i < 4; i++)
#pragma unroll
        for (int j = 0; j < 4; j++) { acch[i][j][0] = 0u; acch[i][j][1] = 0u; }

    load(0);
    load(1);
    for (int kt = 0; kt < nkc; kt++) {
        asm volatile("cp.async.wait_group 1;" ::: "memory");
        __syncthreads();
        if (kt + 2 < nk) load(kt + 2);
        else asm volatile("cp.async.commit_group;" ::: "memory");
        int st = kt % 3;
        uint32_t as = smb + st * SSTAGE + (wm * 64 + (lane & 15)) * STR + (lane >> 4) * 16;
        uint32_t bs = smb + 3 * SSTAGE + st * SSTAGE + (wn * 32 + (lane & 15)) * STR + (lane >> 4) * 16;
#pragma unroll
        for (int kk = 0; kk < 2; kk++) {
            uint32_t a[4][4], bb[2][4];
#pragma unroll
            for (int mt = 0; mt < 4; mt++) ldm4(a[mt], as + mt * 16 * STR + kk * 32);
#pragma unroll
            for (int nt = 0; nt < 2; nt++) ldm4(bb[nt], bs + nt * 16 * STR + kk * 32);
#pragma unroll
            for (int mt = 0; mt < 4; mt++)
#pragma unroll
                for (int n8 = 0; n8 < 4; n8++)
                    mma16hh(acch[mt][n8], a[mt], bb[n8 >> 1][n8 & 1], bb[n8 >> 1][(n8 & 1) + 2]);
        }
    }
    float accf[4][4][4];
#pragma unroll
    for (int mt = 0; mt < 4; mt++)
#pragma unroll
        for (int n8 = 0; n8 < 4; n8++) {
            float2 c0 = __half22float2(*(__half2*)&acch[mt][n8][0]);
            float2 c1 = __half22float2(*(__half2*)&acch[mt][n8][1]);
            accf[mt][n8][0] = c0.x * ISC;
            accf[mt][n8][1] = c0.y * ISC;
            accf[mt][n8][2] = c1.x * ISC;
            accf[mt][n8][3] = c1.y * ISC;
        }
    for (int kt = nkc; kt < nk; kt++) {
        asm volatile("cp.async.wait_group 1;" ::: "memory");
        __syncthreads();
        if (kt + 2 < nk) load(kt + 2);
        else asm volatile("cp.async.commit_group;" ::: "memory");
        int st = kt % 3;
        uint32_t as = smb + st * SSTAGE + (wm * 64 + (lane & 15)) * STR + (lane >> 4) * 16;
        uint32_t bs = smb + 3 * SSTAGE + st * SSTAGE + (wn * 32 + (lane & 15)) * STR + (lane >> 4) * 16;
#pragma unroll
        for (int kk = 0; kk < 2; kk++) {
            uint32_t a[4][4], bb[2][4];
#pragma unroll
            for (int mt = 0; mt < 4; mt++) ldm4(a[mt], as + mt * 16 * STR + kk * 32);
#pragma unroll
            for (int nt = 0; nt < 2; nt++) ldm4(bb[nt], bs + nt * 16 * STR + kk * 32);
#pragma unroll
            for (int mt = 0; mt < 4; mt++)
#pragma unroll
                for (int n8 = 0; n8 < 4; n8++)
                    mma16h(accf[mt][n8], a[mt], bb[n8 >> 1][n8 & 1], bb[n8 >> 1][(n8 & 1) + 2]);
        }
    }

    // epilogue: per-warp 32-k group max -> exp -> fp16 P, partial (m, sum)
    __half* Pb = g_P16 + (size_t)bz * 4096 * 4096;
    int g = blockIdx.x * 4 + wn;
#pragma unroll
    for (int mt = 0; mt < 4; mt++) {
#pragma unroll
        for (int h = 0; h < 2; h++) {
            float m = -3.4e38f;
#pragma unroll
            for (int n8 = 0; n8 < 4; n8++)
                m = fmaxf(m, fmaxf(accf[mt][n8][2 * h], accf[mt][n8][2 * h + 1]));
            m = fmaxf(m, __shfl_xor_sync(0xFFFFFFFF, m, 1));
            m = fmaxf(m, __shfl_xor_sync(0xFFFFFFFF, m, 2));
            int row = m0 + wm * 64 + mt * 16 + h * 8 + (lane >> 2);
            float s = 0.f;
#pragma unroll
            for (int n8 = 0; n8 < 4; n8++) {
                float e0 = fexp(accf[mt][n8][2 * h] - m);
                float e1 = fexp(accf[mt][n8][2 * h + 1] - m);
                s += e0 + e1;
                int col = n0 + wn * 32 + n8 * 8 + (lane & 3) * 2;
                *(__half2*)&Pb[(size_t)row * 4096 + col] = __floats2half2_rn(e0, e1);
            }
            s += __shfl_xor_sync(0xFFFFFFFF, s, 1);
            s += __shfl_xor_sync(0xFFFFFFFF, s, 2);
            if ((lane & 3) == 0) {
                size_t o = ((size_t)bz * 128 + g) * 4096 + row;
                g_pm[o] = m;
                g_ps[o] = s;
            }
        }
    }
}

// combine 128 group partials + border key (8 sbp partials) -> m, 1/Z, bw
__global__ void sm_combine() {
    int i = blockIdx.x * 256 + threadIdx.x;
    int b = i >> 12, q = i & 4095;
    float sbv = 0.f;
#pragma unroll
    for (int j = 0; j < 8; j++) sbv += g_sbp[j * (NB * NPIX) + i];
    float mg = sbv;
#pragma unroll 8
    for (int t = 0; t < 128; t++)
        mg = fmaxf(mg, g_pm[((size_t)b * 128 + t) * 4096 + q]);
    float Z = 260.f * fexp(sbv - mg);
    float eb = Z;
#pragma unroll 8
    for (int t = 0; t < 128; t++) {
        size_t o = ((size_t)b * 128 + t) * 4096 + q;
        Z += fexp(g_pm[o] - mg) * g_ps[o];
    }
    float iz = 1.f / Z;
    g_m[i] = mg;
    g_iz[i] = iz;
    g_bw[i] = eb * iz;
}

// ---------------------------------------------------------------------------
// Fused O GEMM (fp16 data, f32 acc) — R12 form (two-sync, in-iter B fill).
// BM=256, BN=64, BK=32, occ 2.
// ---------------------------------------------------------------------------
#define OASTG (256*STR)
#define OB0   (3*OASTG)
#define OBSTG (64*STR)
#define GSMEM_O (OB0 + 2*OBSTG)

__global__ __launch_bounds__(256, 2) void gemm_o(float* __restrict__ Cout)
{
    extern __shared__ char sm_[];
    uint32_t smb = smem_u32(sm_);
    int tid = threadIdx.x, lane = tid & 31, wid = tid >> 5;
    int wm = wid >> 1, wn = wid & 1;
    int b = blockIdx.z;
    int n0 = blockIdx.x * 64;
    const __half* Vb = g_vf + (size_t)b * NC * NPIX;
    const int nk = 128;

    int fq = tid >> 2, fqt = tid & 3;
    int q = n0 + fq;
    float mq = g_m[b * 4096 + q];
    float izq = g_iz[b * 4096 + q];
    const __half* Pq = g_P16 + ((size_t)b * 4096 + q) * 4096 + fqt * 8;
    const float* pmq = g_pm + (size_t)b * 128 * 4096 + q;

    auto loadA = [&](int kt) {
        int st = kt % 3;
#pragma unroll
        for (int u = 0; u < 4; u++) {
            int e = tid + u * 256;
            int row = e >> 2, ch = e & 3;
            cpa16(smb + st * OASTG + row * STR + ch * 16,
                  Vb + (size_t)row * 4096 + kt * 32 + ch * 8);
        }
        asm volatile("cp.async.commit_group;" ::: "memory");
    };

    float acc[4][4][4];
#pragma unroll
    for (int i = 0; i < 4; i++)
#pragma unroll
        for (int j = 0; j < 4; j++)
#pragma unroll
            for (int r = 0; r < 4; r++) acc[i][j][r] = 0.f;

    uint4 pf;
    float pmv;
    loadA(0);
    loadA(1);
    pf = *(const uint4*)Pq;
    pmv = pmq[0];

    for (int kt = 0; kt < nk; kt++) {
        asm volatile("cp.async.wait_group 1;" ::: "memory");
        __syncthreads();
        {
            float sc = fexp(pmv - mq) * izq;
            __half2 s2 = __float2half2_rn(sc);
            __half2* ph = (__half2*)&pf;
            uint4 o;
            __half2* oh = (__half2*)&o;
            oh[0] = __hmul2(ph[0], s2);
            oh[1] = __hmul2(ph[1], s2);
            oh[2] = __hmul2(ph[2], s2);
            oh[3] = __hmul2(ph[3], s2);
            *(uint4*)(sm_ + OB0 + (kt & 1) * OBSTG + fq * STR + fqt * 16) = o;
        }
        if (kt + 1 < nk) {
            pf = *(const uint4*)(Pq + (kt + 1) * 32);
            pmv = pmq[(size_t)(kt + 1) * 4096];
        }
        if (kt + 2 < nk) loadA(kt + 2);
        else asm volatile("cp.async.commit_group;" ::: "memory");
        __syncthreads();

        int st = kt % 3, b2 = kt & 1;
        uint32_t as_ = smb + st * OASTG + (wm * 64 + (lane & 15)) * STR + (lane >> 4) * 16;
        uint32_t bs_ = smb + OB0 + b2 * OBSTG + (wn * 32 + (lane & 15)) * STR + (lane >> 4) * 16;
#pragma unroll
        for (int kk = 0; kk < 2; kk++) {
            uint32_t a[4][4], bb[2][4];
#pragma unroll
            for (int mt = 0; mt < 4; mt++) ldm4(a[mt], as_ + mt * 16 * STR + kk * 32);
#pragma unroll
            for (int nt = 0; nt < 2; nt++) ldm4(bb[nt], bs_ + nt * 16 * STR + kk * 32);
#pragma unroll
            for (int mt = 0; mt < 4; mt++)
#pragma unroll
                for (int n8 = 0; n8 < 4; n8++)
                    mma16h(acc[mt][n8], a[mt], bb[n8 >> 1][n8 & 1], bb[n8 >> 1][(n8 & 1) + 2]);
        }
    }

    float* Cb = Cout + (size_t)b * NC * NPIX;
    const float* bwp = g_bw + (size_t)b * 4096;
#pragma unroll
    for (int mt = 0; mt < 4; mt++) {
        int row = wm * 64 + mt * 16 + (lane >> 2);
        float vb0 = g_vbv[row], vb1 = g_vbv[row + 8];
#pragma unroll
        for (int n8 = 0; n8 < 4; n8++) {
            int col = n0 + wn * 32 + n8 * 8 + (lane & 3) * 2;
            float w0 = bwp[col], w1 = bwp[col + 1];
            float2 v0, v1;
            v0.x = fmaf(w0, vb0, acc[mt][n8][0]); v0.y = fmaf(w1, vb0, acc[mt][n8][1]);
            v1.x = fmaf(w0, vb1, acc[mt][n8][2]); v1.y = fmaf(w1, vb1, acc[mt][n8][3]);
            *(float2*)&Cb[(size_t)row * 4096 + col] = v0;
            *(float2*)&Cb[(size_t)(row + 8) * 4096 + col] = v1;
        }
    }
}

// ---- prep kernels ----
// zero only the 260 border positions of each 66x66 grid (both buffers)
__global__ void zero_border() {
    int idx = blockIdx.x * 256 + threadIdx.x;    // NB*260*32 uint4 slots
    if (idx >= NB * 260 * 32) return;
    int u = idx & 31;
    int pi = (idx >> 5) % 260;
    int b = idx / (260 * 32);
    int y, x;
    if (pi < 66)       { y = 0;  x = pi; }
    else if (pi < 132) { y = 65; x = pi - 66; }
    else if (pi < 196) { y = pi - 132 + 1; x = 0; }
    else               { y = pi - 196 + 1; x = 65; }
    size_t o = ((size_t)b * 4356 + y * 66 + x) * 32 + u;
    ((uint4*)g_xt_h)[o] = make_uint4(0, 0, 0, 0);
    ((uint4*)g_xt_l)[o] = make_uint4(0, 0, 0, 0);
}

__global__ void xt_fill(const float* __restrict__ x) {
    __shared__ float tile[32][33];
    int b = blockIdx.z;
    int p0 = blockIdx.x * 32, c0 = blockIdx.y * 32;
    int tx = threadIdx.x, ty = threadIdx.y;
    const float* s = x + (size_t)b * NC * NPIX;
    for (int j = 0; j < 32; j += 8)
        tile[ty + j][tx] = s[(size_t)(c0 + ty + j) * NPIX + p0 + tx];
    __syncthreads();
    for (int j = 0; j < 32; j += 8) {
        int p = p0 + ty + j, y = p >> 6, xx = p & 63;
        size_t o = ((size_t)b * 4356 + (y + 1) * 66 + (xx + 1)) * 256 + c0 + tx;
        __half h, l;
        split2h(tile[tx][ty + j], h, l);
        g_xt_h[o] = h;
        g_xt_l[o] = l;
    }
}

// merged weight split: grid.y 0 -> Wq (blocks [h|l*256|h], k=t*256+c), 1 -> Wk, 2 -> Wv
__global__ void wsplit_all(const float* __restrict__ Wq, const float* __restrict__ Wk,
                           const float* __restrict__ Wv) {
    int t = blockIdx.y;
    int idx = blockIdx.x * 256 + threadIdx.x;
    if (t == 0) {
        if (idx >= NC * 2304) return;
        int m = idx / 2304, r = idx % 2304;
        int c = r / 9, tp = r % 9;
        __half h, l;
        split2h(Wq[idx], h, l);
        size_t base = (size_t)m * 6912 + tp * 256 + c;
        g_wqh[base] = h;
        g_wqh[base + 2304] = l;
        g_wqh[base + 4608] = h;
    } else {
        if (idx >= NC * NC) return;
        const float* w = (t == 1) ? Wk : Wv;
        __half* o = (t == 1) ? g_wkh : g_wvh;
        int m = idx / NC, c = idx % NC;
        __half h, l;
        split2h(w[idx], h, l);
        size_t base = (size_t)m * 768 + c;
        o[base] = h;
        o[base + 256] = l;
        o[base + 512] = h;
    }
}

// merged transpose/split: z = which*4 + b; which 0 = Q (patA, border partials), 1 = K
__global__ void tsplit2() {
    __shared__ float tile[32][33];
    __shared__ float sbred[8][32];
    int z = blockIdx.z;
    int which = z >> 2;
    int b = z & 3;
    const float* src = which ? g_kc : g_qc;
    __half* dst = which ? g_kth : g_qth;
    const float* aa = g_a + which * 256;
    const float* ad = g_dd + which * 256;
    int p0 = blockIdx.x * 32, c0 = blockIdx.y * 32;
    int tx = threadIdx.x, ty = threadIdx.y;
    const float* s = src + (size_t)b * NC * NPIX;
    for (int j = 0; j < 32; j += 8) {
        float a = aa[c0 + ty + j], d = ad[c0 + ty + j];
        tile[ty + j][tx] = fmaf(a, s[(size_t)(c0 + ty + j) * NPIX + p0 + tx], d);
    }
    __syncthreads();
    for (int j = 0; j < 32; j += 8) {
        __half h, l;
        split2h(tile[tx][ty + j], h, l);
        __half* o = dst + ((size_t)b * 4096 + p0 + ty + j) * 768 + c0 + tx;
        o[0] = which ? l : h;
        o[256] = which ? h : l;
        o[512] = h;
    }
    if (which == 0) {
        float part = 0.f;
#pragma unroll
        for (int c = ty; c < 32; c += 8)
            part = fmaf(g_kbv[c0 + c], tile[c][tx], part);
        sbred[ty][tx] = part;
        __syncthreads();
        if (ty == 0) {
            float sum = 0.f;
#pragma unroll
            for (int j = 0; j < 8; j++) sum += sbred[j][tx];
            g_sbp[(size_t)blockIdx.y * (NB * NPIX) + b * NPIX + p0 + tx] = sum;
        }
    }
}

__global__ void vf_k() {
    size_t i4 = (size_t)blockIdx.x * 256 + threadIdx.x;
    size_t e = i4 * 4;
    int c = (int)((e >> 12) & 255);
    float a = g_a[512 + c], d = g_dd[512 + c];
    float4 v = *(float4*)(g_vc + e);
    __half h[4];
    h[0] = __float2half(fmaf(a, v.x, d));
    h[1] = __float2half(fmaf(a, v.y, d));
    h[2] = __float2half(fmaf(a, v.z, d));
    h[3] = __float2half(fmaf(a, v.w, d));
    *(uint2*)(g_vf + e) = *(uint2*)h;
}

// tiny stats: sum 128 conv partials per channel
__global__ void stats_k(const float* __restrict__ bq, const float* __restrict__ gq, const float* __restrict__ betaq,
                        const float* __restrict__ bk, const float* __restrict__ gk, const float* __restrict__ betak,
                        const float* __restrict__ bv, const float* __restrict__ gv, const float* __restrict__ betav)
{
    int t = blockIdx.x;
    int c = threadIdx.x;
    float S1f = 0.f, S2f = 0.f;
    for (int j = 0; j < 128; j++) {
        S1f += g_psum1[(t * 128 + j) * 256 + c];
        S2f += g_psum2[(t * 128 + j) * 256 + c];
    }
    double S1 = S1f, S2 = S2f, cnt = 16384.0;
    float bias = (t == 0) ? bq[c] : (t == 1) ? bk[c] : bv[c];
    float g    = (t == 0) ? gq[c] : (t == 1) ? gk[c] : gv[c];
    float be   = (t == 0) ? betaq[c] : (t == 1) ? betak[c] : betav[c];
    if (t > 0) {
        cnt = 17424.0;
        S1 += 1040.0 * (double)bias;
        S2 += 1040.0 * (double)bias * (double)bias;
    }
    double mean = S1 / cnt;
    double var = S2 / cnt - mean * mean;
    float a = g * rsqrtf((float)var + 1e-5f);
    float d = be - a * (float)mean;
    g_a[t * NC + c] = a;
    g_dd[t * NC + c] = d;
    if (t == 1) g_kbv[c] = fmaf(a, bias, d);
    if (t == 2) g_vbv[c] = fmaf(a, bias, d);
}

// ---------------------------------------------------------------------------
extern "C" void kernel_launch(void* const* d_in, const int* in_sizes, int n_in,
                              void* d_out, int out_size)
{
    const float* x     = (const float*)d_in[0];
    const float* Wq    = (const float*)d_in[1];
    const float* bq    = (const float*)d_in[2];
    const float* gq    = (const float*)d_in[3];
    const float* betaq = (const float*)d_in[4];
    const float* Wk    = (const float*)d_in[5];
    const float* bk    = (const float*)d_in[6];
    const float* gk    = (const float*)d_in[7];
    const float* betak = (const float*)d_in[8];
    const float* Wv    = (const float*)d_in[9];
    const float* bv    = (const float*)d_in[10];
    const float* gv    = (const float*)d_in[11];
    const float* betav = (const float*)d_in[12];
    float* out = (float*)d_out;

    cudaFuncSetAttribute(gemm_conv<9>, cudaFuncAttributeMaxDynamicSharedMemorySize, GSMEM_C);
    cudaFuncSetAttribute(gemm_conv<1>, cudaFuncAttributeMaxDynamicSharedMemorySize, GSMEM_C);
    cudaFuncSetAttribute(gemm_s, cudaFuncAttributeMaxDynamicSharedMemorySize, GSMEM_S);
    cudaFuncSetAttribute(gemm_o, cudaFuncAttributeMaxDynamicSharedMemorySize, GSMEM_O);

    __half *p_wqh, *p_wkh, *p_wvh, *p_qth, *p_kth;
    float *p_qc, *p_kc, *p_vc;
    cudaGetSymbolAddress((void**)&p_wqh, g_wqh);
    cudaGetSymbolAddress((void**)&p_wkh, g_wkh);
    cudaGetSymbolAddress((void**)&p_wvh, g_wvh);
    cudaGetSymbolAddress((void**)&p_qth, g_qth);
    cudaGetSymbolAddress((void**)&p_kth, g_kth);
    cudaGetSymbolAddress((void**)&p_qc,  g_qc);
    cudaGetSymbolAddress((void**)&p_kc,  g_kc);
    cudaGetSymbolAddress((void**)&p_vc,  g_vc);

    // 1. border zero + padded transposed hi/lo x (fp16) + merged weight splits
    zero_border<<<(NB * 260 * 32 + 255) / 256, 256>>>();
    xt_fill<<<dim3(128, 8, NB), dim3(32, 8)>>>(x);
    wsplit_all<<<dim3(2304, 3), 256>>>(Wq, Wk, Wv);

    // 2. convs (implicit im2col, fp16 hi/lo, mixed-acc, single-sync)
    gemm_conv<9><<<dim3(32, 2, NB), 256, GSMEM_C>>>(p_wqh, p_qc, bq, 0);
    gemm_conv<1><<<dim3(32, 2, NB), 256, GSMEM_C>>>(p_wkh, p_kc, bk, 1);
    gemm_conv<1><<<dim3(32, 2, NB), 256, GSMEM_C>>>(p_wvh, p_vc, bv, 2);

    // 3. BN stats (tiny) + merged Q/K transpose-splits (Q emits border partials) + V fp16
    stats_k<<<3, 256>>>(bq, gq, betaq, bk, gk, betak, bv, gv, betav);
    tsplit2<<<dim3(128, 8, 8), dim3(32, 8)>>>();
    vf_k<<<(int)(((size_t)NB * NC * NPIX / 4) / 256), 256>>>();

    // 4. S GEMM (fp16 hi/lo, mixed-acc, single-sync) -> fp16 exp-tiles + partials
    gemm_s<<<dim3(32, 32, NB), 256, GSMEM_S>>>(p_qth, p_kth);

    // 5. combine partials -> m, 1/Z, bw
    sm_combine<<<64, 256>>>();

    // 6. fused O GEMM (fp16, f32 acc, occ 2)
    gemm_o<<<dim3(64, 1, NB), 256, GSMEM_O>>>(out);
}